// round 5
// baseline (speedup 1.0000x reference)
#include <cuda_runtime.h>

#define HH 56
#define WW 56
#define CC 64
#define BB 4
#define HWP 3136           // 56*56
#define NPIX (BB*HWP)      // 12544

// ---------------- packed f32x2 helpers ----------------
__device__ __forceinline__ unsigned long long fma2(unsigned long long a, unsigned long long b, unsigned long long c) {
    unsigned long long d;
    asm("fma.rn.f32x2 %0, %1, %2, %3;" : "=l"(d) : "l"(a), "l"(b), "l"(c));
    return d;
}
__device__ __forceinline__ unsigned long long mul2(unsigned long long a, unsigned long long b) {
    unsigned long long d;
    asm("mul.rn.f32x2 %0, %1, %2;" : "=l"(d) : "l"(a), "l"(b));
    return d;
}

// ---------------- scratch (device globals; no allocations) ----------------
__device__ __align__(16) float g_xcl [NPIX*CC];      // x in NHWC
__device__ __align__(16) float g_off3[NPIX*98];      // offset3 [pix][98]
__device__ __align__(16) float g_off2[NPIX*50];      // offset2 [pix][50]
__device__ __align__(16) float g_out1[NPIX*CC];      // out1 NHWC
__device__ __align__(16) float g_out2[NPIX*CC];      // out2 NHWC
__device__ __align__(16) float g_w7t [49*CC];        // w7 transposed [k][c]
__device__ __align__(16) float g_w5t [25*CC];        // w5 transposed [k][c]
__device__ __align__(16) float2 g_wp3[288*49];       // conv3 weight pairs [(ic*9+j)][o]
__device__ __align__(16) float2 g_wp2[288*25];       // conv2 weight pairs
__device__ __align__(16) float2 g_bp3[49];
__device__ __align__(16) float2 g_bp2[25];
__device__ __align__(16) float g_part1[BB*32*CC];
__device__ __align__(16) float g_part2[BB*32*CC];
__device__ __align__(16) float g_attn [BB*CC];

// ---------------- weight prep (grid-parallel) ----------------
__global__ void k_wprep(const float* __restrict__ w7, const float* __restrict__ w5,
                        const float* __restrict__ w_off3, const float* __restrict__ b_off3,
                        const float* __restrict__ w_off2, const float* __restrict__ b_off2) {
    int tid = blockIdx.x * blockDim.x + threadIdx.x;
    int nthr = gridDim.x * blockDim.x;
    for (int i = tid; i < CC*49; i += nthr) {
        int c = i / 49, k = i - c*49;
        g_w7t[k*CC + c] = w7[i];
    }
    for (int i = tid; i < CC*25; i += nthr) {
        int c = i / 25, k = i - c*25;
        g_w5t[k*CC + c] = w5[i];
    }
    for (int i = tid; i < 288*49; i += nthr) {
        int r = i / 49, o = i - r*49;
        int ic = r / 9, j = r - ic*9;
        g_wp3[i] = make_float2(w_off3[(o*32 + ic)*9 + j], w_off3[((o+49)*32 + ic)*9 + j]);
    }
    for (int i = tid; i < 288*25; i += nthr) {
        int r = i / 25, o = i - r*25;
        int ic = r / 9, j = r - ic*9;
        g_wp2[i] = make_float2(w_off2[(o*32 + ic)*9 + j], w_off2[((o+25)*32 + ic)*9 + j]);
    }
    if (tid < 49) g_bp3[tid] = make_float2(b_off3[tid], b_off3[tid+49]);
    if (tid >= 64 && tid < 89) g_bp2[tid-64] = make_float2(b_off2[tid-64], b_off2[tid-64+25]);
}

// ---------------- NCHW -> NHWC transpose of x ----------------
__global__ void k_nchw2cl(const float* __restrict__ x) {
    __shared__ float tile[CC][33];
    int b  = blockIdx.x / 98;
    int p0 = (blockIdx.x % 98) * 32;
    int tid = threadIdx.x;
#pragma unroll
    for (int it = 0; it < 8; it++) {
        int idx = tid + it*256;
        int c = idx >> 5, pp = idx & 31;
        tile[c][pp] = x[((size_t)(b*CC + c))*HWP + p0 + pp];
    }
    __syncthreads();
    int c2 = tid & 63;
#pragma unroll
    for (int it = 0; it < 8; it++) {
        int pp2 = (tid >> 6) + it*4;
        g_xcl[((size_t)(b*HWP + p0 + pp2))*CC + c2] = tile[c2][pp2];
    }
}

// ---------------- fused grouped 3x3 convs, 8-pixel tiles, f32x2 -----------
// block = (b, y, x-tile of 8); 96 threads. Thread t<49: conv3 pair (t, t+49);
// 49<=t<74: conv2 pair (t-49, t-24).
__global__ __launch_bounds__(96) void k_conv_fused(const float* __restrict__ xcl,
                                                   float* __restrict__ out3,
                                                   float* __restrict__ out2) {
    __shared__ float2 xsp[3][10][32];   // [dy][col][ic]: (x[ic], x[ic+32])
    int bid = blockIdx.x;
    int xt = bid % 7;
    int y  = (bid / 7) % HH;
    int b  = bid / (7*HH);
    int x0 = xt * 8;
    int tid = threadIdx.x;

    // stage: 3*10*32 = 960 pairs
    for (int i = tid; i < 960; i += 96) {
        int ic  = i & 31;
        int col = (i >> 5) % 10;
        int dy  = i / 320;
        int yy = y + dy - 1;
        int xx = x0 + col - 1;
        float v0 = 0.f, v1 = 0.f;
        if (yy >= 0 && yy < HH && xx >= 0 && xx < WW) {
            size_t base = ((size_t)((b*HH + yy)*WW + xx))*CC;
            v0 = xcl[base + ic];
            v1 = xcl[base + 32 + ic];
        }
        xsp[dy][col][ic] = make_float2(v0, v1);
    }
    __syncthreads();

    int t = tid;
    if (t < 74) {
        bool is3 = (t < 49);
        int o = is3 ? t : t - 49;
        int stride = is3 ? 49 : 25;
        const unsigned long long* wrow = is3 ? ((const unsigned long long*)g_wp3) + o
                                             : ((const unsigned long long*)g_wp2) + o;
        float2 bp = is3 ? g_bp3[o] : g_bp2[o];
        unsigned long long bdup;
        asm("mov.b64 %0, {%1, %2};" : "=l"(bdup) : "f"(bp.x), "f"(bp.y));

        unsigned long long acc[8];
#pragma unroll
        for (int p = 0; p < 8; p++) acc[p] = bdup;

#pragma unroll 2
        for (int ic = 0; ic < 32; ic++) {
            unsigned long long w2[9];
#pragma unroll
            for (int j = 0; j < 9; j++)
                w2[j] = wrow[(ic*9 + j)*stride];
#pragma unroll
            for (int dy = 0; dy < 3; dy++) {
                unsigned long long xm[10];
#pragma unroll
                for (int col = 0; col < 10; col++)
                    xm[col] = *(const unsigned long long*)&xsp[dy][col][ic];
#pragma unroll
                for (int dx = 0; dx < 3; dx++) {
                    unsigned long long wv = w2[dy*3 + dx];
#pragma unroll
                    for (int p = 0; p < 8; p++)
                        acc[p] = fma2(wv, xm[p+dx], acc[p]);
                }
            }
        }

        size_t pix = (size_t)(b*HH + y)*WW + x0;
        union { unsigned long long u; float f[2]; } cv;
        if (is3) {
#pragma unroll
            for (int p = 0; p < 8; p++) {
                cv.u = acc[p];
                out3[(pix + p)*98 + o]      = cv.f[0];
                out3[(pix + p)*98 + o + 49] = cv.f[1];
            }
        } else {
#pragma unroll
            for (int p = 0; p < 8; p++) {
                cv.u = acc[p];
                out2[(pix + p)*50 + o]      = cv.f[0];
                out2[(pix + p)*50 + o + 25] = cv.f[1];
            }
        }
    }
}

// ---------------- deformable depthwise conv (manual 2-tap MLP) ------------
// 128 threads = 4 warps; warp owns TWO pixels (half-warp each); lane owns
// 4 channels. Each iteration loads BOTH taps' gathers before any math.
template<int K, int PAD, int DIL>
__global__ __launch_bounds__(128) void k_deform(
                         const float* __restrict__ src,   // NHWC
                         const float* __restrict__ off,   // [pix][2*K*K]
                         const float* __restrict__ wt,    // [K*K][C]
                         const float* __restrict__ bias,
                         float* __restrict__ out) {       // NHWC
    constexpr int K2 = K*K;
    constexpr int OFFC = 2*K2;
    __shared__ float4 scoef[4][2][K2][2];  // {c00,c00,c01,c01},{c10,c10,c11,c11}
    __shared__ int4   saddr[4][2][K2];
    int wid  = threadIdx.x >> 5;
    int lane = threadIdx.x & 31;
    int gp0 = blockIdx.x*8 + wid*2;

    // phase 1: per-tap coefficient + address precompute for both pixels
    for (int tpos = lane; tpos < 2*K2; tpos += 32) {
        int pl = tpos / K2;
        int k  = tpos - pl*K2;
        int gp = gp0 + pl;
        int b = gp / HWP;
        int p = gp - b*HWP;
        int y = p / WW;
        int x = p - y*WW;
        float2 o2 = *(const float2*)(off + (size_t)gp*OFFC + 2*k);
        int ky = k / K, kx = k - ky*K;
        float py = (float)(y - PAD + DIL*ky) + o2.x;
        float px = (float)(x - PAD + DIL*kx) + o2.y;
        float fy = floorf(py), fx = floorf(px);
        float ly = py - fy,  lx = px - fx;
        float hy = 1.f - ly, hx = 1.f - lx;
        int iy0 = (int)fy, ix0 = (int)fx;
        int iy1 = iy0 + 1, ix1 = ix0 + 1;
        bool vy0 = (unsigned)iy0 < HH;
        bool vy1 = (unsigned)iy1 < HH;
        bool vx0 = (unsigned)ix0 < WW;
        bool vx1 = (unsigned)ix1 < WW;
        float c00 = (vy0 && vx0) ? hy*hx : 0.f;
        float c01 = (vy0 && vx1) ? hy*lx : 0.f;
        float c10 = (vy1 && vx0) ? ly*hx : 0.f;
        float c11 = (vy1 && vx1) ? ly*lx : 0.f;
        int jy0 = min(max(iy0,0), HH-1), jy1 = min(max(iy1,0), HH-1);
        int jx0 = min(max(ix0,0), WW-1), jx1 = min(max(ix1,0), WW-1);
        scoef[wid][pl][k][0] = make_float4(c00, c00, c01, c01);
        scoef[wid][pl][k][1] = make_float4(c10, c10, c11, c11);
        saddr[wid][pl][k] = make_int4((jy0*WW + jx0)*CC, (jy0*WW + jx1)*CC,
                                      (jy1*WW + jx0)*CC, (jy1*WW + jx1)*CC);
    }
    __syncwarp();

    int half = lane >> 4;
    int c4 = (lane & 15) * 4;
    int gp = gp0 + half;
    int b = gp / HWP;
    const float* sb = src + (size_t)b*HWP*CC + c4;
    const float* wp = wt + c4;

    ulonglong2 acc = *(const ulonglong2*)(bias + c4);

#pragma unroll
    for (int k = 0; k < K2 - 1; k += 2) {
        // ---- all loads for taps k and k+1 first (10 LDG.128 in flight) ----
        int4 adA = saddr[wid][half][k];
        int4 adB = saddr[wid][half][k+1];
        ulonglong2 a00 = *(const ulonglong2*)(sb + adA.x);
        ulonglong2 a01 = *(const ulonglong2*)(sb + adA.y);
        ulonglong2 a10 = *(const ulonglong2*)(sb + adA.z);
        ulonglong2 a11 = *(const ulonglong2*)(sb + adA.w);
        ulonglong2 awv = *(const ulonglong2*)(wp + k*CC);
        ulonglong2 b00 = *(const ulonglong2*)(sb + adB.x);
        ulonglong2 b01 = *(const ulonglong2*)(sb + adB.y);
        ulonglong2 b10 = *(const ulonglong2*)(sb + adB.z);
        ulonglong2 b11 = *(const ulonglong2*)(sb + adB.w);
        ulonglong2 bwv = *(const ulonglong2*)(wp + (k+1)*CC);
        ulonglong2 cA0 = *((const ulonglong2*)&scoef[wid][half][k][0]);
        ulonglong2 cA1 = *((const ulonglong2*)&scoef[wid][half][k][1]);
        ulonglong2 cB0 = *((const ulonglong2*)&scoef[wid][half][k+1][0]);
        ulonglong2 cB1 = *((const ulonglong2*)&scoef[wid][half][k+1][1]);
        // ---- tap k math ----
        unsigned long long t0 = mul2(cA0.x, a00.x);
        t0 = fma2(cA0.y, a01.x, t0);
        t0 = fma2(cA1.x, a10.x, t0);
        t0 = fma2(cA1.y, a11.x, t0);
        acc.x = fma2(awv.x, t0, acc.x);
        unsigned long long t1 = mul2(cA0.x, a00.y);
        t1 = fma2(cA0.y, a01.y, t1);
        t1 = fma2(cA1.x, a10.y, t1);
        t1 = fma2(cA1.y, a11.y, t1);
        acc.y = fma2(awv.y, t1, acc.y);
        // ---- tap k+1 math ----
        unsigned long long u0 = mul2(cB0.x, b00.x);
        u0 = fma2(cB0.y, b01.x, u0);
        u0 = fma2(cB1.x, b10.x, u0);
        u0 = fma2(cB1.y, b11.x, u0);
        acc.x = fma2(bwv.x, u0, acc.x);
        unsigned long long u1 = mul2(cB0.x, b00.y);
        u1 = fma2(cB0.y, b01.y, u1);
        u1 = fma2(cB1.x, b10.y, u1);
        u1 = fma2(cB1.y, b11.y, u1);
        acc.y = fma2(bwv.y, u1, acc.y);
    }
    {   // tail tap (K2 is odd)
        constexpr int k = K2 - 1;
        int4 ad = saddr[wid][half][k];
        ulonglong2 v00 = *(const ulonglong2*)(sb + ad.x);
        ulonglong2 v01 = *(const ulonglong2*)(sb + ad.y);
        ulonglong2 v10 = *(const ulonglong2*)(sb + ad.z);
        ulonglong2 v11 = *(const ulonglong2*)(sb + ad.w);
        ulonglong2 wv  = *(const ulonglong2*)(wp + k*CC);
        ulonglong2 cA = *((const ulonglong2*)&scoef[wid][half][k][0]);
        ulonglong2 cB = *((const ulonglong2*)&scoef[wid][half][k][1]);
        unsigned long long t0 = mul2(cA.x, v00.x);
        t0 = fma2(cA.y, v01.x, t0);
        t0 = fma2(cB.x, v10.x, t0);
        t0 = fma2(cB.y, v11.x, t0);
        acc.x = fma2(wv.x, t0, acc.x);
        unsigned long long t1 = mul2(cA.x, v00.y);
        t1 = fma2(cA.y, v01.y, t1);
        t1 = fma2(cB.x, v10.y, t1);
        t1 = fma2(cB.y, v11.y, t1);
        acc.y = fma2(wv.y, t1, acc.y);
    }
    *(ulonglong2*)(out + (size_t)gp*CC + c4) = acc;
}

// ---------------- GAP partial sums (float4, 256 threads) ----------------
__global__ void k_gap_part() {
    int b = blockIdx.x >> 5;
    int chunk = blockIdx.x & 31;
    int q = threadIdx.x & 15;
    int s = threadIdx.x >> 4;
    float4 a1 = make_float4(0,0,0,0), a2 = make_float4(0,0,0,0);
    for (int p = s; p < 98; p += 16) {
        size_t base = ((size_t)(b*HWP) + chunk*98 + p)*CC + q*4;
        float4 v1 = *(const float4*)(g_out1 + base);
        float4 v2 = *(const float4*)(g_out2 + base);
        a1.x += v1.x; a1.y += v1.y; a1.z += v1.z; a1.w += v1.w;
        a2.x += v2.x; a2.y += v2.y; a2.z += v2.z; a2.w += v2.w;
    }
    __shared__ float4 sh1[16][16], sh2[16][16];
    sh1[s][q] = a1; sh2[s][q] = a2;
    __syncthreads();
    if (s == 0) {
#pragma unroll
        for (int j = 1; j < 16; j++) {
            float4 v1 = sh1[j][q], v2 = sh2[j][q];
            a1.x += v1.x; a1.y += v1.y; a1.z += v1.z; a1.w += v1.w;
            a2.x += v2.x; a2.y += v2.y; a2.z += v2.z; a2.w += v2.w;
        }
        *(float4*)(g_part1 + (b*32 + chunk)*CC + q*4) = a1;
        *(float4*)(g_part2 + (b*32 + chunk)*CC + q*4) = a2;
    }
}

// ---------------- GAP finalize + softmax attn ----------------
__global__ void k_gap_final() {
    int b = blockIdx.x;
    int c = threadIdx.x;
    float s1 = 0.f, s2 = 0.f;
    for (int j = 0; j < 32; j++) {
        s1 += g_part1[(b*32 + j)*CC + c];
        s2 += g_part2[(b*32 + j)*CC + c];
    }
    float g1 = s1 * (1.f/3136.f), g2 = s2 * (1.f/3136.f);
    float m = fmaxf(g1, g2);
    float e1 = expf(g1 - m), e2 = expf(g2 - m);
    g_attn[b*CC + c] = e1 / (e1 + e2);
}

// ---------------- combine + NHWC -> NCHW ----------------
__global__ void k_combine(float* __restrict__ out) {
    __shared__ float tile[CC][33];
    int b  = blockIdx.x / 98;
    int p0 = (blockIdx.x % 98) * 32;
    int tid = threadIdx.x;
    int c = tid & 63;
    float a = g_attn[b*CC + c];
#pragma unroll
    for (int it = 0; it < 8; it++) {
        int pp = (tid >> 6) + it*4;
        size_t idx = ((size_t)(b*HWP + p0 + pp))*CC + c;
        float v1 = g_out1[idx], v2 = g_out2[idx];
        tile[c][pp] = v1*a + v2*(1.f - a);
    }
    __syncthreads();
#pragma unroll
    for (int it = 0; it < 8; it++) {
        int idx = tid + it*256;
        int cc = idx >> 5, pp = idx & 31;
        out[((size_t)(b*CC + cc))*HWP + p0 + pp] = tile[cc][pp];
    }
}

// ---------------- launcher ----------------
extern "C" void kernel_launch(void* const* d_in, const int* in_sizes, int n_in,
                              void* d_out, int out_size) {
    const float* x      = (const float*)d_in[0];
    const float* w_off3 = (const float*)d_in[1];
    const float* b_off3 = (const float*)d_in[2];
    const float* w_off2 = (const float*)d_in[3];
    const float* b_off2 = (const float*)d_in[4];
    const float* w7     = (const float*)d_in[5];
    const float* b7     = (const float*)d_in[6];
    const float* w5     = (const float*)d_in[7];
    const float* b5     = (const float*)d_in[8];
    float* out = (float*)d_out;

    float *p_xcl, *p_off3, *p_off2, *p_out1, *p_out2, *p_w7t, *p_w5t;
    cudaGetSymbolAddress((void**)&p_xcl,  g_xcl);
    cudaGetSymbolAddress((void**)&p_off3, g_off3);
    cudaGetSymbolAddress((void**)&p_off2, g_off2);
    cudaGetSymbolAddress((void**)&p_out1, g_out1);
    cudaGetSymbolAddress((void**)&p_out2, g_out2);
    cudaGetSymbolAddress((void**)&p_w7t,  g_w7t);
    cudaGetSymbolAddress((void**)&p_w5t,  g_w5t);

    k_wprep<<<64, 256>>>(w7, w5, w_off3, b_off3, w_off2, b_off2);
    k_nchw2cl<<<BB*98, 256>>>(x);

    k_conv_fused<<<BB*HH*7, 96>>>(p_xcl, p_off3, p_off2);

    k_deform<7,9,3><<<NPIX/8, 128>>>(p_xcl,  p_off3, p_w7t, b7, p_out1);
    k_deform<5,6,3><<<NPIX/8, 128>>>(p_out1, p_off2, p_w5t, b5, p_out2);

    k_gap_part<<<BB*32, 256>>>();
    k_gap_final<<<BB, 64>>>();
    k_combine<<<BB*98, 256>>>(out);
}

// round 6
// speedup vs baseline: 1.3267x; 1.3267x over previous
#include <cuda_runtime.h>
#include <cuda_fp16.h>

#define HH 56
#define WW 56
#define CC 64
#define BB 4
#define HWP 3136           // 56*56
#define NPIX (BB*HWP)      // 12544

// ---------------- packed f32x2 helpers ----------------
__device__ __forceinline__ unsigned long long fma2(unsigned long long a, unsigned long long b, unsigned long long c) {
    unsigned long long d;
    asm("fma.rn.f32x2 %0, %1, %2, %3;" : "=l"(d) : "l"(a), "l"(b), "l"(c));
    return d;
}
__device__ __forceinline__ unsigned long long mul2(unsigned long long a, unsigned long long b) {
    unsigned long long d;
    asm("mul.rn.f32x2 %0, %1, %2;" : "=l"(d) : "l"(a), "l"(b));
    return d;
}
// half2 (as u32) -> packed f32x2 in 64-bit reg
__device__ __forceinline__ unsigned long long h2f2(unsigned int h) {
    __half2 hh = *reinterpret_cast<__half2*>(&h);
    float2 f = __half22float2(hh);
    unsigned long long d;
    asm("mov.b64 %0, {%1, %2};" : "=l"(d) : "f"(f.x), "f"(f.y));
    return d;
}

// ---------------- scratch (device globals; no allocations) ----------------
__device__ __align__(16) float g_xcl [NPIX*CC];      // x in NHWC fp32 (conv source)
__device__ __align__(16) __half g_xh [NPIX*CC];      // x in NHWC fp16 (deform1 gather src)
__device__ __align__(16) __half g_o1h[NPIX*CC];      // out1 NHWC fp16 (deform2 gather src)
__device__ __align__(16) float g_off3[NPIX*98];      // offset3 [pix][98]
__device__ __align__(16) float g_off2[NPIX*50];      // offset2 [pix][50]
__device__ __align__(16) float g_out1[NPIX*CC];      // out1 NHWC fp32
__device__ __align__(16) float g_out2[NPIX*CC];      // out2 NHWC fp32
__device__ __align__(16) float g_w7t [49*CC];        // w7 transposed [k][c]
__device__ __align__(16) float g_w5t [25*CC];        // w5 transposed [k][c]
__device__ __align__(16) float2 g_wp3[288*49];       // conv3 weight pairs [(ic*9+j)][o]
__device__ __align__(16) float2 g_wp2[288*25];       // conv2 weight pairs
__device__ __align__(16) float2 g_bp3[49];
__device__ __align__(16) float2 g_bp2[25];
__device__ __align__(16) float g_part1[BB*32*CC];
__device__ __align__(16) float g_part2[BB*32*CC];
__device__ __align__(16) float g_attn [BB*CC];

// ---------------- weight prep (grid-parallel) ----------------
__global__ void k_wprep(const float* __restrict__ w7, const float* __restrict__ w5,
                        const float* __restrict__ w_off3, const float* __restrict__ b_off3,
                        const float* __restrict__ w_off2, const float* __restrict__ b_off2) {
    int tid = blockIdx.x * blockDim.x + threadIdx.x;
    int nthr = gridDim.x * blockDim.x;
    for (int i = tid; i < CC*49; i += nthr) {
        int c = i / 49, k = i - c*49;
        g_w7t[k*CC + c] = w7[i];
    }
    for (int i = tid; i < CC*25; i += nthr) {
        int c = i / 25, k = i - c*25;
        g_w5t[k*CC + c] = w5[i];
    }
    for (int i = tid; i < 288*49; i += nthr) {
        int r = i / 49, o = i - r*49;
        int ic = r / 9, j = r - ic*9;
        g_wp3[i] = make_float2(w_off3[(o*32 + ic)*9 + j], w_off3[((o+49)*32 + ic)*9 + j]);
    }
    for (int i = tid; i < 288*25; i += nthr) {
        int r = i / 25, o = i - r*25;
        int ic = r / 9, j = r - ic*9;
        g_wp2[i] = make_float2(w_off2[(o*32 + ic)*9 + j], w_off2[((o+25)*32 + ic)*9 + j]);
    }
    if (tid < 49) g_bp3[tid] = make_float2(b_off3[tid], b_off3[tid+49]);
    if (tid >= 64 && tid < 89) g_bp2[tid-64] = make_float2(b_off2[tid-64], b_off2[tid-64+25]);
}

// ---------------- NCHW -> NHWC transpose of x (fp32 + fp16 copies) --------
__global__ void k_nchw2cl(const float* __restrict__ x) {
    __shared__ float tile[CC][33];
    int b  = blockIdx.x / 98;
    int p0 = (blockIdx.x % 98) * 32;
    int tid = threadIdx.x;
#pragma unroll
    for (int it = 0; it < 8; it++) {
        int idx = tid + it*256;
        int c = idx >> 5, pp = idx & 31;
        tile[c][pp] = x[((size_t)(b*CC + c))*HWP + p0 + pp];
    }
    __syncthreads();
    int c2 = tid & 63;
#pragma unroll
    for (int it = 0; it < 8; it++) {
        int pp2 = (tid >> 6) + it*4;
        float v = tile[c2][pp2];
        size_t idx = ((size_t)(b*HWP + p0 + pp2))*CC + c2;
        g_xcl[idx] = v;
        g_xh[idx]  = __float2half(v);
    }
}

// ---------------- fused grouped 3x3 convs, 14-pixel tiles, f32x2 ----------
__global__ __launch_bounds__(96) void k_conv_fused(const float* __restrict__ xcl,
                                                   float* __restrict__ out3,
                                                   float* __restrict__ out2) {
    __shared__ float2 xsp[3][16][32];   // [dy][col][ic]: (x[ic], x[ic+32])
    int bid = blockIdx.x;
    int xt = bid & 3;
    int y  = (bid >> 2) % HH;
    int b  = bid / (4*HH);
    int x0 = xt * 14;
    int tid = threadIdx.x;

#pragma unroll
    for (int it = 0; it < 16; it++) {
        int i = tid + it*96;
        int ic  = i & 31;
        int col = (i >> 5) & 15;
        int dy  = i >> 9;
        int yy = y + dy - 1;
        int xx = x0 + col - 1;
        float v0 = 0.f, v1 = 0.f;
        if (yy >= 0 && yy < HH && xx >= 0 && xx < WW) {
            size_t base = ((size_t)((b*HH + yy)*WW + xx))*CC;
            v0 = xcl[base + ic];
            v1 = xcl[base + 32 + ic];
        }
        xsp[dy][col][ic] = make_float2(v0, v1);
    }
    __syncthreads();

    int t = tid;
    if (t < 74) {
        bool is3 = (t < 49);
        int o = is3 ? t : t - 49;
        int stride = is3 ? 49 : 25;
        const unsigned long long* wrow = is3 ? ((const unsigned long long*)g_wp3) + o
                                             : ((const unsigned long long*)g_wp2) + o;
        float2 bp = is3 ? g_bp3[o] : g_bp2[o];
        unsigned long long bdup;
        asm("mov.b64 %0, {%1, %2};" : "=l"(bdup) : "f"(bp.x), "f"(bp.y));

        unsigned long long acc[14];
#pragma unroll
        for (int p = 0; p < 14; p++) acc[p] = bdup;

#pragma unroll 2
        for (int ic = 0; ic < 32; ic++) {
            unsigned long long w2[9];
#pragma unroll
            for (int j = 0; j < 9; j++)
                w2[j] = wrow[(ic*9 + j)*stride];
#pragma unroll
            for (int dy = 0; dy < 3; dy++) {
                unsigned long long xm[16];
#pragma unroll
                for (int col = 0; col < 16; col++)
                    xm[col] = *(const unsigned long long*)&xsp[dy][col][ic];
#pragma unroll
                for (int dx = 0; dx < 3; dx++) {
                    unsigned long long wv = w2[dy*3 + dx];
#pragma unroll
                    for (int p = 0; p < 14; p++)
                        acc[p] = fma2(wv, xm[p+dx], acc[p]);
                }
            }
        }

        size_t pix = (size_t)(b*HH + y)*WW + x0;
        union { unsigned long long u; float f[2]; } cv;
        if (is3) {
#pragma unroll
            for (int p = 0; p < 14; p++) {
                cv.u = acc[p];
                out3[(pix + p)*98 + o]      = cv.f[0];
                out3[(pix + p)*98 + o + 49] = cv.f[1];
            }
        } else {
#pragma unroll
            for (int p = 0; p < 14; p++) {
                cv.u = acc[p];
                out2[(pix + p)*50 + o]      = cv.f[0];
                out2[(pix + p)*50 + o + 25] = cv.f[1];
            }
        }
    }
}

// ---------------- deformable depthwise conv (fp16 gather, fp32 math) ------
// 128 threads = 4 warps; warp owns TWO pixels (half-warp each); lane owns
// 4 channels (8B fp16 per corner -> 1 line per pixel-corner).
template<int K, int PAD, int DIL, bool WRITE_H>
__global__ __launch_bounds__(128) void k_deform(
                         const __half* __restrict__ src,  // NHWC fp16
                         const float* __restrict__ off,   // [pix][2*K*K]
                         const float* __restrict__ wt,    // [K*K][C] fp32
                         const float* __restrict__ bias,
                         float* __restrict__ outf,        // NHWC fp32
                         __half* __restrict__ outh) {     // NHWC fp16 (optional)
    constexpr int K2 = K*K;
    constexpr int OFFC = 2*K2;
    __shared__ float4 scoef[4][2][K2][2];  // {c00,c00,c01,c01},{c10,c10,c11,c11}
    __shared__ int4   saddr[4][2][K2];
    int wid  = threadIdx.x >> 5;
    int lane = threadIdx.x & 31;
    int gp0 = blockIdx.x*8 + wid*2;

    // phase 1: per-tap coefficient + address precompute for both pixels
    for (int tpos = lane; tpos < 2*K2; tpos += 32) {
        int pl = tpos / K2;
        int k  = tpos - pl*K2;
        int gp = gp0 + pl;
        int b = gp / HWP;
        int p = gp - b*HWP;
        int y = p / WW;
        int x = p - y*WW;
        float2 o2 = *(const float2*)(off + (size_t)gp*OFFC + 2*k);
        int ky = k / K, kx = k - ky*K;
        float py = (float)(y - PAD + DIL*ky) + o2.x;
        float px = (float)(x - PAD + DIL*kx) + o2.y;
        float fy = floorf(py), fx = floorf(px);
        float ly = py - fy,  lx = px - fx;
        float hy = 1.f - ly, hx = 1.f - lx;
        int iy0 = (int)fy, ix0 = (int)fx;
        int iy1 = iy0 + 1, ix1 = ix0 + 1;
        bool vy0 = (unsigned)iy0 < HH;
        bool vy1 = (unsigned)iy1 < HH;
        bool vx0 = (unsigned)ix0 < WW;
        bool vx1 = (unsigned)ix1 < WW;
        float c00 = (vy0 && vx0) ? hy*hx : 0.f;
        float c01 = (vy0 && vx1) ? hy*lx : 0.f;
        float c10 = (vy1 && vx0) ? ly*hx : 0.f;
        float c11 = (vy1 && vx1) ? ly*lx : 0.f;
        int jy0 = min(max(iy0,0), HH-1), jy1 = min(max(iy1,0), HH-1);
        int jx0 = min(max(ix0,0), WW-1), jx1 = min(max(ix1,0), WW-1);
        scoef[wid][pl][k][0] = make_float4(c00, c00, c01, c01);
        scoef[wid][pl][k][1] = make_float4(c10, c10, c11, c11);
        saddr[wid][pl][k] = make_int4((jy0*WW + jx0)*CC, (jy0*WW + jx1)*CC,
                                      (jy1*WW + jx0)*CC, (jy1*WW + jx1)*CC);
    }
    __syncwarp();

    int half_ = lane >> 4;
    int c4 = (lane & 15) * 4;
    int gp = gp0 + half_;
    int b = gp / HWP;
    const __half* sb = src + (size_t)b*HWP*CC + c4;
    const float* wp = wt + c4;

    ulonglong2 acc = *(const ulonglong2*)(bias + c4);

#pragma unroll
    for (int k = 0; k < K2; k++) {
        int4 ad = saddr[wid][half_][k];
        uint2 r00 = *(const uint2*)(sb + ad.x);
        uint2 r01 = *(const uint2*)(sb + ad.y);
        uint2 r10 = *(const uint2*)(sb + ad.z);
        uint2 r11 = *(const uint2*)(sb + ad.w);
        ulonglong2 wv = *(const ulonglong2*)(wp + k*CC);
        ulonglong2 cA = *((const ulonglong2*)&scoef[wid][half_][k][0]);
        ulonglong2 cB = *((const ulonglong2*)&scoef[wid][half_][k][1]);
        // channels 0-1 of the quad
        unsigned long long t0 = mul2(cA.x, h2f2(r00.x));
        t0 = fma2(cA.y, h2f2(r01.x), t0);
        t0 = fma2(cB.x, h2f2(r10.x), t0);
        t0 = fma2(cB.y, h2f2(r11.x), t0);
        acc.x = fma2(wv.x, t0, acc.x);
        // channels 2-3 of the quad
        unsigned long long t1 = mul2(cA.x, h2f2(r00.y));
        t1 = fma2(cA.y, h2f2(r01.y), t1);
        t1 = fma2(cB.x, h2f2(r10.y), t1);
        t1 = fma2(cB.y, h2f2(r11.y), t1);
        acc.y = fma2(wv.y, t1, acc.y);
    }
    *(ulonglong2*)(outf + (size_t)gp*CC + c4) = acc;
    if (WRITE_H) {
        union { unsigned long long u; float f[2]; } a0, a1;
        a0.u = acc.x; a1.u = acc.y;
        __half2 h0 = __floats2half2_rn(a0.f[0], a0.f[1]);
        __half2 h1 = __floats2half2_rn(a1.f[0], a1.f[1]);
        uint2 st;
        st.x = *reinterpret_cast<unsigned int*>(&h0);
        st.y = *reinterpret_cast<unsigned int*>(&h1);
        *(uint2*)(outh + (size_t)gp*CC + c4) = st;
    }
}

// ---------------- GAP partial sums (float4, 256 threads) ----------------
__global__ void k_gap_part() {
    int b = blockIdx.x >> 5;
    int chunk = blockIdx.x & 31;
    int q = threadIdx.x & 15;
    int s = threadIdx.x >> 4;
    float4 a1 = make_float4(0,0,0,0), a2 = make_float4(0,0,0,0);
    for (int p = s; p < 98; p += 16) {
        size_t base = ((size_t)(b*HWP) + chunk*98 + p)*CC + q*4;
        float4 v1 = *(const float4*)(g_out1 + base);
        float4 v2 = *(const float4*)(g_out2 + base);
        a1.x += v1.x; a1.y += v1.y; a1.z += v1.z; a1.w += v1.w;
        a2.x += v2.x; a2.y += v2.y; a2.z += v2.z; a2.w += v2.w;
    }
    __shared__ float4 sh1[16][16], sh2[16][16];
    sh1[s][q] = a1; sh2[s][q] = a2;
    __syncthreads();
    if (s == 0) {
#pragma unroll
        for (int j = 1; j < 16; j++) {
            float4 v1 = sh1[j][q], v2 = sh2[j][q];
            a1.x += v1.x; a1.y += v1.y; a1.z += v1.z; a1.w += v1.w;
            a2.x += v2.x; a2.y += v2.y; a2.z += v2.z; a2.w += v2.w;
        }
        *(float4*)(g_part1 + (b*32 + chunk)*CC + q*4) = a1;
        *(float4*)(g_part2 + (b*32 + chunk)*CC + q*4) = a2;
    }
}

// ---------------- GAP finalize + softmax attn ----------------
__global__ void k_gap_final() {
    int b = blockIdx.x;
    int c = threadIdx.x;
    float s1 = 0.f, s2 = 0.f;
    for (int j = 0; j < 32; j++) {
        s1 += g_part1[(b*32 + j)*CC + c];
        s2 += g_part2[(b*32 + j)*CC + c];
    }
    float g1 = s1 * (1.f/3136.f), g2 = s2 * (1.f/3136.f);
    float m = fmaxf(g1, g2);
    float e1 = expf(g1 - m), e2 = expf(g2 - m);
    g_attn[b*CC + c] = e1 / (e1 + e2);
}

// ---------------- combine + NHWC -> NCHW ----------------
__global__ void k_combine(float* __restrict__ out) {
    __shared__ float tile[CC][33];
    int b  = blockIdx.x / 98;
    int p0 = (blockIdx.x % 98) * 32;
    int tid = threadIdx.x;
    int c = tid & 63;
    float a = g_attn[b*CC + c];
#pragma unroll
    for (int it = 0; it < 8; it++) {
        int pp = (tid >> 6) + it*4;
        size_t idx = ((size_t)(b*HWP + p0 + pp))*CC + c;
        float v1 = g_out1[idx], v2 = g_out2[idx];
        tile[c][pp] = v1*a + v2*(1.f - a);
    }
    __syncthreads();
#pragma unroll
    for (int it = 0; it < 8; it++) {
        int idx = tid + it*256;
        int cc = idx >> 5, pp = idx & 31;
        out[((size_t)(b*CC + cc))*HWP + p0 + pp] = tile[cc][pp];
    }
}

// ---------------- launcher ----------------
extern "C" void kernel_launch(void* const* d_in, const int* in_sizes, int n_in,
                              void* d_out, int out_size) {
    const float* x      = (const float*)d_in[0];
    const float* w_off3 = (const float*)d_in[1];
    const float* b_off3 = (const float*)d_in[2];
    const float* w_off2 = (const float*)d_in[3];
    const float* b_off2 = (const float*)d_in[4];
    const float* w7     = (const float*)d_in[5];
    const float* b7     = (const float*)d_in[6];
    const float* w5     = (const float*)d_in[7];
    const float* b5     = (const float*)d_in[8];
    float* out = (float*)d_out;

    float *p_xcl, *p_off3, *p_off2, *p_out1, *p_out2, *p_w7t, *p_w5t;
    __half *p_xh, *p_o1h;
    cudaGetSymbolAddress((void**)&p_xcl,  g_xcl);
    cudaGetSymbolAddress((void**)&p_xh,   g_xh);
    cudaGetSymbolAddress((void**)&p_o1h,  g_o1h);
    cudaGetSymbolAddress((void**)&p_off3, g_off3);
    cudaGetSymbolAddress((void**)&p_off2, g_off2);
    cudaGetSymbolAddress((void**)&p_out1, g_out1);
    cudaGetSymbolAddress((void**)&p_out2, g_out2);
    cudaGetSymbolAddress((void**)&p_w7t,  g_w7t);
    cudaGetSymbolAddress((void**)&p_w5t,  g_w5t);

    k_wprep<<<64, 256>>>(w7, w5, w_off3, b_off3, w_off2, b_off2);
    k_nchw2cl<<<BB*98, 256>>>(x);

    k_conv_fused<<<BB*HH*4, 96>>>(p_xcl, p_off3, p_off2);

    k_deform<7,9,3,true ><<<NPIX/8, 128>>>(p_xh,  p_off3, p_w7t, b7, p_out1, p_o1h);
    k_deform<5,6,3,false><<<NPIX/8, 128>>>(p_o1h, p_off2, p_w5t, b5, p_out2, nullptr);

    k_gap_part<<<BB*32, 256>>>();
    k_gap_final<<<BB, 64>>>();
    k_combine<<<BB*98, 256>>>(out);
}

// round 7
// speedup vs baseline: 1.3548x; 1.0212x over previous
#include <cuda_runtime.h>
#include <cuda_fp16.h>

#define HH 56
#define WW 56
#define CC 64
#define BB 4
#define HWP 3136           // 56*56
#define NPIX (BB*HWP)      // 12544
#define NDB  (NPIX/8)      // deform blocks = 1568 (392 per batch)

// ---------------- packed f32x2 helpers ----------------
__device__ __forceinline__ unsigned long long fma2(unsigned long long a, unsigned long long b, unsigned long long c) {
    unsigned long long d;
    asm("fma.rn.f32x2 %0, %1, %2, %3;" : "=l"(d) : "l"(a), "l"(b), "l"(c));
    return d;
}
__device__ __forceinline__ unsigned long long mul2(unsigned long long a, unsigned long long b) {
    unsigned long long d;
    asm("mul.rn.f32x2 %0, %1, %2;" : "=l"(d) : "l"(a), "l"(b));
    return d;
}
__device__ __forceinline__ __half2 u2h(unsigned int v) { return *reinterpret_cast<__half2*>(&v); }
__device__ __forceinline__ unsigned int h2u(__half2 h) { return *reinterpret_cast<unsigned int*>(&h); }
// half2 -> packed f32x2 in 64-bit reg
__device__ __forceinline__ unsigned long long h2f2(__half2 hh) {
    float2 f = __half22float2(hh);
    unsigned long long d;
    asm("mov.b64 %0, {%1, %2};" : "=l"(d) : "f"(f.x), "f"(f.y));
    return d;
}

// ---------------- scratch (device globals; no allocations) ----------------
__device__ __align__(16) float g_xcl [NPIX*CC];      // x in NHWC fp32 (conv source)
__device__ __align__(16) __half g_xh [NPIX*CC];      // x in NHWC fp16 (deform1 gather src)
__device__ __align__(16) __half g_o1h[NPIX*CC];      // out1 NHWC fp16 (deform2 gather src)
__device__ __align__(16) float g_off3[NPIX*98];      // offset3 [pix][98]
__device__ __align__(16) float g_off2[NPIX*50];      // offset2 [pix][50]
__device__ __align__(16) float g_out1[NPIX*CC];      // out1 NHWC fp32
__device__ __align__(16) float g_out2[NPIX*CC];      // out2 NHWC fp32
__device__ __align__(16) float g_w7t [49*CC];        // w7 transposed [k][c]
__device__ __align__(16) float g_w5t [25*CC];        // w5 transposed [k][c]
__device__ __align__(16) float2 g_wp3[288*49];       // conv3 weight pairs [(ic*9+j)][o]
__device__ __align__(16) float2 g_wp2[288*25];       // conv2 weight pairs
__device__ __align__(16) float2 g_bp3[49];
__device__ __align__(16) float2 g_bp2[25];
__device__ __align__(16) float g_bs1[NDB*CC];        // per-block GAP partials (out1)
__device__ __align__(16) float g_bs2[NDB*CC];        // per-block GAP partials (out2)
__device__ __align__(16) float g_attn [BB*CC];

// ---------------- weight prep (grid-parallel) ----------------
__global__ void k_wprep(const float* __restrict__ w7, const float* __restrict__ w5,
                        const float* __restrict__ w_off3, const float* __restrict__ b_off3,
                        const float* __restrict__ w_off2, const float* __restrict__ b_off2) {
    int tid = blockIdx.x * blockDim.x + threadIdx.x;
    int nthr = gridDim.x * blockDim.x;
    for (int i = tid; i < CC*49; i += nthr) {
        int c = i / 49, k = i - c*49;
        g_w7t[k*CC + c] = w7[i];
    }
    for (int i = tid; i < CC*25; i += nthr) {
        int c = i / 25, k = i - c*25;
        g_w5t[k*CC + c] = w5[i];
    }
    for (int i = tid; i < 288*49; i += nthr) {
        int r = i / 49, o = i - r*49;
        int ic = r / 9, j = r - ic*9;
        g_wp3[i] = make_float2(w_off3[(o*32 + ic)*9 + j], w_off3[((o+49)*32 + ic)*9 + j]);
    }
    for (int i = tid; i < 288*25; i += nthr) {
        int r = i / 25, o = i - r*25;
        int ic = r / 9, j = r - ic*9;
        g_wp2[i] = make_float2(w_off2[(o*32 + ic)*9 + j], w_off2[((o+25)*32 + ic)*9 + j]);
    }
    if (tid < 49) g_bp3[tid] = make_float2(b_off3[tid], b_off3[tid+49]);
    if (tid >= 64 && tid < 89) g_bp2[tid-64] = make_float2(b_off2[tid-64], b_off2[tid-64+25]);
}

// ---------------- NCHW -> NHWC transpose of x (fp32 + fp16 copies) --------
__global__ void k_nchw2cl(const float* __restrict__ x) {
    __shared__ float tile[CC][33];
    int b  = blockIdx.x / 98;
    int p0 = (blockIdx.x % 98) * 32;
    int tid = threadIdx.x;
#pragma unroll
    for (int it = 0; it < 8; it++) {
        int idx = tid + it*256;
        int c = idx >> 5, pp = idx & 31;
        tile[c][pp] = x[((size_t)(b*CC + c))*HWP + p0 + pp];
    }
    __syncthreads();
    int c2 = tid & 63;
#pragma unroll
    for (int it = 0; it < 8; it++) {
        int pp2 = (tid >> 6) + it*4;
        float v = tile[c2][pp2];
        size_t idx = ((size_t)(b*HWP + p0 + pp2))*CC + c2;
        g_xcl[idx] = v;
        g_xh[idx]  = __float2half(v);
    }
}

// ---------------- fused grouped 3x3 convs, 14-pixel tiles, f32x2 ----------
__global__ __launch_bounds__(96) void k_conv_fused(const float* __restrict__ xcl,
                                                   float* __restrict__ out3,
                                                   float* __restrict__ out2) {
    __shared__ float2 xsp[3][16][32];   // [dy][col][ic]: (x[ic], x[ic+32])
    int bid = blockIdx.x;
    int xt = bid & 3;
    int y  = (bid >> 2) % HH;
    int b  = bid / (4*HH);
    int x0 = xt * 14;
    int tid = threadIdx.x;

#pragma unroll
    for (int it = 0; it < 16; it++) {
        int i = tid + it*96;
        int ic  = i & 31;
        int col = (i >> 5) & 15;
        int dy  = i >> 9;
        int yy = y + dy - 1;
        int xx = x0 + col - 1;
        float v0 = 0.f, v1 = 0.f;
        if (yy >= 0 && yy < HH && xx >= 0 && xx < WW) {
            size_t base = ((size_t)((b*HH + yy)*WW + xx))*CC;
            v0 = xcl[base + ic];
            v1 = xcl[base + 32 + ic];
        }
        xsp[dy][col][ic] = make_float2(v0, v1);
    }
    __syncthreads();

    int t = tid;
    if (t < 74) {
        bool is3 = (t < 49);
        int o = is3 ? t : t - 49;
        int stride = is3 ? 49 : 25;
        const unsigned long long* wrow = is3 ? ((const unsigned long long*)g_wp3) + o
                                             : ((const unsigned long long*)g_wp2) + o;
        float2 bp = is3 ? g_bp3[o] : g_bp2[o];
        unsigned long long bdup;
        asm("mov.b64 %0, {%1, %2};" : "=l"(bdup) : "f"(bp.x), "f"(bp.y));

        unsigned long long acc[14];
#pragma unroll
        for (int p = 0; p < 14; p++) acc[p] = bdup;

#pragma unroll 2
        for (int ic = 0; ic < 32; ic++) {
            unsigned long long w2[9];
#pragma unroll
            for (int j = 0; j < 9; j++)
                w2[j] = wrow[(ic*9 + j)*stride];
#pragma unroll
            for (int dy = 0; dy < 3; dy++) {
                unsigned long long xm[16];
#pragma unroll
                for (int col = 0; col < 16; col++)
                    xm[col] = *(const unsigned long long*)&xsp[dy][col][ic];
#pragma unroll
                for (int dx = 0; dx < 3; dx++) {
                    unsigned long long wv = w2[dy*3 + dx];
#pragma unroll
                    for (int p = 0; p < 14; p++)
                        acc[p] = fma2(wv, xm[p+dx], acc[p]);
                }
            }
        }

        size_t pix = (size_t)(b*HH + y)*WW + x0;
        union { unsigned long long u; float f[2]; } cv;
        if (is3) {
#pragma unroll
            for (int p = 0; p < 14; p++) {
                cv.u = acc[p];
                out3[(pix + p)*98 + o]      = cv.f[0];
                out3[(pix + p)*98 + o + 49] = cv.f[1];
            }
        } else {
#pragma unroll
            for (int p = 0; p < 14; p++) {
                cv.u = acc[p];
                out2[(pix + p)*50 + o]      = cv.f[0];
                out2[(pix + p)*50 + o + 25] = cv.f[1];
            }
        }
    }
}

// ---------------- deformable depthwise conv (fp16 bilinear, GAP fused) ----
// 128 threads = 4 warps; warp owns TWO pixels (half-warp each); lane owns
// 4 fp16 channels. Bilinear fully in HFMA2 with separable masked coefs;
// single convert to f32x2 for weight-accumulate. Epilogue reduces block
// partial GAP sums (deterministic).
template<int K, int PAD, int DIL, bool WRITE_H>
__global__ __launch_bounds__(128) void k_deform(
                         const __half* __restrict__ src,  // NHWC fp16
                         const float* __restrict__ off,   // [pix][2*K*K]
                         const float* __restrict__ wt,    // [K*K][C] fp32
                         const float* __restrict__ bias,
                         float* __restrict__ outf,        // NHWC fp32
                         __half* __restrict__ outh,       // NHWC fp16 (optional)
                         float* __restrict__ bsum) {      // [NDB][CC] partials
    constexpr int K2 = K*K;
    constexpr int OFFC = 2*K2;
    __shared__ uint4 scoefh[4][2][K2];     // {hx2, lx2, hy2, ly2} (masked, splatted)
    __shared__ int4  saddr [4][2][K2];
    __shared__ float4 sred[4][2][16];
    int wid  = threadIdx.x >> 5;
    int lane = threadIdx.x & 31;
    int gp0 = blockIdx.x*8 + wid*2;

    // phase 1: per-tap coefficient + address precompute for both pixels
    for (int tpos = lane; tpos < 2*K2; tpos += 32) {
        int pl = tpos / K2;
        int k  = tpos - pl*K2;
        int gp = gp0 + pl;
        int b = gp / HWP;
        int p = gp - b*HWP;
        int y = p / WW;
        int x = p - y*WW;
        float2 o2 = *(const float2*)(off + (size_t)gp*OFFC + 2*k);
        int ky = k / K, kx = k - ky*K;
        float py = (float)(y - PAD + DIL*ky) + o2.x;
        float px = (float)(x - PAD + DIL*kx) + o2.y;
        float fy = floorf(py), fx = floorf(px);
        float ly = py - fy,  lx = px - fx;
        float hy = 1.f - ly, hx = 1.f - lx;
        int iy0 = (int)fy, ix0 = (int)fx;
        int iy1 = iy0 + 1, ix1 = ix0 + 1;
        // separable masked coefs
        float hxm = ((unsigned)ix0 < WW) ? hx : 0.f;
        float lxm = ((unsigned)ix1 < WW) ? lx : 0.f;
        float hym = ((unsigned)iy0 < HH) ? hy : 0.f;
        float lym = ((unsigned)iy1 < HH) ? ly : 0.f;
        int jy0 = min(max(iy0,0), HH-1), jy1 = min(max(iy1,0), HH-1);
        int jx0 = min(max(ix0,0), WW-1), jx1 = min(max(ix1,0), WW-1);
        scoefh[wid][pl][k] = make_uint4(h2u(__float2half2_rn(hxm)),
                                        h2u(__float2half2_rn(lxm)),
                                        h2u(__float2half2_rn(hym)),
                                        h2u(__float2half2_rn(lym)));
        saddr[wid][pl][k] = make_int4((jy0*WW + jx0)*CC, (jy0*WW + jx1)*CC,
                                      (jy1*WW + jx0)*CC, (jy1*WW + jx1)*CC);
    }
    __syncwarp();

    int half_ = lane >> 4;
    int c4 = (lane & 15) * 4;
    int gp = gp0 + half_;
    int b = gp / HWP;
    const __half* sb = src + (size_t)b*HWP*CC + c4;
    const float* wp = wt + c4;

    ulonglong2 acc = *(const ulonglong2*)(bias + c4);

#pragma unroll
    for (int k = 0; k < K2; k++) {
        int4 ad = saddr[wid][half_][k];
        uint2 r00 = *(const uint2*)(sb + ad.x);
        uint2 r01 = *(const uint2*)(sb + ad.y);
        uint2 r10 = *(const uint2*)(sb + ad.z);
        uint2 r11 = *(const uint2*)(sb + ad.w);
        ulonglong2 wv = *(const ulonglong2*)(wp + k*CC);
        uint4 cf = scoefh[wid][half_][k];
        __half2 HX = u2h(cf.x), LX = u2h(cf.y), HY = u2h(cf.z), LY = u2h(cf.w);
        // channels 0-1
        {
            __half2 top = __hfma2(LX, u2h(r01.x), __hmul2(HX, u2h(r00.x)));
            __half2 bot = __hfma2(LX, u2h(r11.x), __hmul2(HX, u2h(r10.x)));
            __half2 val = __hfma2(LY, bot, __hmul2(HY, top));
            acc.x = fma2(wv.x, h2f2(val), acc.x);
        }
        // channels 2-3
        {
            __half2 top = __hfma2(LX, u2h(r01.y), __hmul2(HX, u2h(r00.y)));
            __half2 bot = __hfma2(LX, u2h(r11.y), __hmul2(HX, u2h(r10.y)));
            __half2 val = __hfma2(LY, bot, __hmul2(HY, top));
            acc.y = fma2(wv.y, h2f2(val), acc.y);
        }
    }
    *(ulonglong2*)(outf + (size_t)gp*CC + c4) = acc;

    union { unsigned long long u; float f[2]; } a0, a1;
    a0.u = acc.x; a1.u = acc.y;
    if (WRITE_H) {
        __half2 h0 = __floats2half2_rn(a0.f[0], a0.f[1]);
        __half2 h1 = __floats2half2_rn(a1.f[0], a1.f[1]);
        uint2 st;
        st.x = h2u(h0);
        st.y = h2u(h1);
        *(uint2*)(outh + (size_t)gp*CC + c4) = st;
    }

    // ---- fused GAP partial: per-block channel sums over the 8 pixels ----
    sred[wid][half_][lane & 15] = make_float4(a0.f[0], a0.f[1], a1.f[0], a1.f[1]);
    __syncthreads();
    if (threadIdx.x < 16) {
        float4 s = make_float4(0.f, 0.f, 0.f, 0.f);
#pragma unroll
        for (int w = 0; w < 4; w++)
#pragma unroll
            for (int h = 0; h < 2; h++) {
                float4 v = sred[w][h][threadIdx.x];
                s.x += v.x; s.y += v.y; s.z += v.z; s.w += v.w;
            }
        *(float4*)(bsum + (size_t)blockIdx.x*CC + threadIdx.x*4) = s;
    }
}

// ---------------- GAP finalize + softmax attn (from block partials) -------
__global__ void k_gap_final() {
    // grid = BB, 256 threads: q = ch quad, s = block-stride slot
    int b = blockIdx.x;
    int q = threadIdx.x & 15;
    int s = threadIdx.x >> 4;
    float4 a1 = make_float4(0,0,0,0), a2 = make_float4(0,0,0,0);
    for (int j = s; j < 392; j += 16) {
        size_t idx = (size_t)(b*392 + j)*CC + q*4;
        float4 v1 = *(const float4*)(g_bs1 + idx);
        float4 v2 = *(const float4*)(g_bs2 + idx);
        a1.x += v1.x; a1.y += v1.y; a1.z += v1.z; a1.w += v1.w;
        a2.x += v2.x; a2.y += v2.y; a2.z += v2.z; a2.w += v2.w;
    }
    __shared__ float4 sh1[16][16], sh2[16][16];
    sh1[s][q] = a1; sh2[s][q] = a2;
    __syncthreads();
    if (s == 0) {
#pragma unroll
        for (int j = 1; j < 16; j++) {
            float4 v1 = sh1[j][q], v2 = sh2[j][q];
            a1.x += v1.x; a1.y += v1.y; a1.z += v1.z; a1.w += v1.w;
            a2.x += v2.x; a2.y += v2.y; a2.z += v2.z; a2.w += v2.w;
        }
        float s1[4] = {a1.x, a1.y, a1.z, a1.w};
        float s2[4] = {a2.x, a2.y, a2.z, a2.w};
#pragma unroll
        for (int i = 0; i < 4; i++) {
            float g1 = s1[i] * (1.f/3136.f), g2 = s2[i] * (1.f/3136.f);
            float m = fmaxf(g1, g2);
            float e1 = expf(g1 - m), e2 = expf(g2 - m);
            g_attn[b*CC + q*4 + i] = e1 / (e1 + e2);
        }
    }
}

// ---------------- combine + NHWC -> NCHW ----------------
__global__ void k_combine(float* __restrict__ out) {
    __shared__ float tile[CC][33];
    int b  = blockIdx.x / 98;
    int p0 = (blockIdx.x % 98) * 32;
    int tid = threadIdx.x;
    int c = tid & 63;
    float a = g_attn[b*CC + c];
#pragma unroll
    for (int it = 0; it < 8; it++) {
        int pp = (tid >> 6) + it*4;
        size_t idx = ((size_t)(b*HWP + p0 + pp))*CC + c;
        float v1 = g_out1[idx], v2 = g_out2[idx];
        tile[c][pp] = v1*a + v2*(1.f - a);
    }
    __syncthreads();
#pragma unroll
    for (int it = 0; it < 8; it++) {
        int idx = tid + it*256;
        int cc = idx >> 5, pp = idx & 31;
        out[((size_t)(b*CC + cc))*HWP + p0 + pp] = tile[cc][pp];
    }
}

// ---------------- launcher ----------------
extern "C" void kernel_launch(void* const* d_in, const int* in_sizes, int n_in,
                              void* d_out, int out_size) {
    const float* x      = (const float*)d_in[0];
    const float* w_off3 = (const float*)d_in[1];
    const float* b_off3 = (const float*)d_in[2];
    const float* w_off2 = (const float*)d_in[3];
    const float* b_off2 = (const float*)d_in[4];
    const float* w7     = (const float*)d_in[5];
    const float* b7     = (const float*)d_in[6];
    const float* w5     = (const float*)d_in[7];
    const float* b5     = (const float*)d_in[8];
    float* out = (float*)d_out;

    float *p_xcl, *p_off3, *p_off2, *p_out1, *p_out2, *p_w7t, *p_w5t, *p_bs1, *p_bs2;
    __half *p_xh, *p_o1h;
    cudaGetSymbolAddress((void**)&p_xcl,  g_xcl);
    cudaGetSymbolAddress((void**)&p_xh,   g_xh);
    cudaGetSymbolAddress((void**)&p_o1h,  g_o1h);
    cudaGetSymbolAddress((void**)&p_off3, g_off3);
    cudaGetSymbolAddress((void**)&p_off2, g_off2);
    cudaGetSymbolAddress((void**)&p_out1, g_out1);
    cudaGetSymbolAddress((void**)&p_out2, g_out2);
    cudaGetSymbolAddress((void**)&p_w7t,  g_w7t);
    cudaGetSymbolAddress((void**)&p_w5t,  g_w5t);
    cudaGetSymbolAddress((void**)&p_bs1,  g_bs1);
    cudaGetSymbolAddress((void**)&p_bs2,  g_bs2);

    k_wprep<<<64, 256>>>(w7, w5, w_off3, b_off3, w_off2, b_off2);
    k_nchw2cl<<<BB*98, 256>>>(x);

    k_conv_fused<<<BB*HH*4, 96>>>(p_xcl, p_off3, p_off2);

    k_deform<7,9,3,true ><<<NDB, 128>>>(p_xh,  p_off3, p_w7t, b7, p_out1, p_o1h,   p_bs1);
    k_deform<5,6,3,false><<<NDB, 128>>>(p_o1h, p_off2, p_w5t, b5, p_out2, nullptr, p_bs2);

    k_gap_final<<<BB, 256>>>();
    k_combine<<<BB*98, 256>>>(out);
}

// round 8
// speedup vs baseline: 1.3557x; 1.0007x over previous
#include <cuda_runtime.h>
#include <cuda_fp16.h>

#define HH 56
#define WW 56
#define CC 64
#define BB 4
#define HWP 3136           // 56*56
#define NPIX (BB*HWP)      // 12544
#define NDB  (NPIX/32)     // deform blocks = 392 (98 per batch)

// ---------------- packed f32x2 helpers ----------------
__device__ __forceinline__ unsigned long long fma2(unsigned long long a, unsigned long long b, unsigned long long c) {
    unsigned long long d;
    asm("fma.rn.f32x2 %0, %1, %2, %3;" : "=l"(d) : "l"(a), "l"(b), "l"(c));
    return d;
}
__device__ __forceinline__ __half2 u2h(unsigned int v) { return *reinterpret_cast<__half2*>(&v); }
__device__ __forceinline__ unsigned int h2u(__half2 h) { return *reinterpret_cast<unsigned int*>(&h); }
// half2 -> packed f32x2 in 64-bit reg
__device__ __forceinline__ unsigned long long h2f2(__half2 hh) {
    float2 f = __half22float2(hh);
    unsigned long long d;
    asm("mov.b64 %0, {%1, %2};" : "=l"(d) : "f"(f.x), "f"(f.y));
    return d;
}

// ---------------- scratch (device globals; no allocations) ----------------
__device__ __align__(16) float g_xcl [NPIX*CC];      // x in NHWC fp32 (conv source)
__device__ __align__(16) __half g_xh [NPIX*CC];      // x in NHWC fp16 (deform1 gather src)
__device__ __align__(16) __half g_o1h[NPIX*CC];      // out1 NHWC fp16 (deform2 gather src)
__device__ __align__(16) float g_off3[NPIX*98];      // offset3 [pix][98]
__device__ __align__(16) float g_off2[NPIX*50];      // offset2 [pix][50]
__device__ __align__(16) float g_out1[NPIX*CC];      // out1 NHWC fp32
__device__ __align__(16) float g_out2[NPIX*CC];      // out2 NHWC fp32
__device__ __align__(16) float g_w7t [49*CC];        // w7 transposed [k][c]
__device__ __align__(16) float g_w5t [25*CC];        // w5 transposed [k][c]
__device__ __align__(16) float2 g_wp3[288*49];       // conv3 weight pairs [(ic*9+j)][o]
__device__ __align__(16) float2 g_wp2[288*25];       // conv2 weight pairs
__device__ __align__(16) float2 g_bp3[49];
__device__ __align__(16) float2 g_bp2[25];
__device__ __align__(16) float g_bs1[NDB*CC];        // per-block GAP partials (out1)
__device__ __align__(16) float g_bs2[NDB*CC];        // per-block GAP partials (out2)
__device__ __align__(16) float g_attn [BB*CC];

// ---------------- weight prep (grid-parallel) ----------------
__global__ void k_wprep(const float* __restrict__ w7, const float* __restrict__ w5,
                        const float* __restrict__ w_off3, const float* __restrict__ b_off3,
                        const float* __restrict__ w_off2, const float* __restrict__ b_off2) {
    int tid = blockIdx.x * blockDim.x + threadIdx.x;
    int nthr = gridDim.x * blockDim.x;
    for (int i = tid; i < CC*49; i += nthr) {
        int c = i / 49, k = i - c*49;
        g_w7t[k*CC + c] = w7[i];
    }
    for (int i = tid; i < CC*25; i += nthr) {
        int c = i / 25, k = i - c*25;
        g_w5t[k*CC + c] = w5[i];
    }
    for (int i = tid; i < 288*49; i += nthr) {
        int r = i / 49, o = i - r*49;
        int ic = r / 9, j = r - ic*9;
        g_wp3[i] = make_float2(w_off3[(o*32 + ic)*9 + j], w_off3[((o+49)*32 + ic)*9 + j]);
    }
    for (int i = tid; i < 288*25; i += nthr) {
        int r = i / 25, o = i - r*25;
        int ic = r / 9, j = r - ic*9;
        g_wp2[i] = make_float2(w_off2[(o*32 + ic)*9 + j], w_off2[((o+25)*32 + ic)*9 + j]);
    }
    if (tid < 49) g_bp3[tid] = make_float2(b_off3[tid], b_off3[tid+49]);
    if (tid >= 64 && tid < 89) g_bp2[tid-64] = make_float2(b_off2[tid-64], b_off2[tid-64+25]);
}

// ---------------- NCHW -> NHWC transpose of x (fp32 + fp16 copies) --------
__global__ void k_nchw2cl(const float* __restrict__ x) {
    __shared__ float tile[CC][33];
    int b  = blockIdx.x / 98;
    int p0 = (blockIdx.x % 98) * 32;
    int tid = threadIdx.x;
#pragma unroll
    for (int it = 0; it < 8; it++) {
        int idx = tid + it*256;
        int c = idx >> 5, pp = idx & 31;
        tile[c][pp] = x[((size_t)(b*CC + c))*HWP + p0 + pp];
    }
    __syncthreads();
    int c2 = tid & 63;
#pragma unroll
    for (int it = 0; it < 8; it++) {
        int pp2 = (tid >> 6) + it*4;
        float v = tile[c2][pp2];
        size_t idx = ((size_t)(b*HWP + p0 + pp2))*CC + c2;
        g_xcl[idx] = v;
        g_xh[idx]  = __float2half(v);
    }
}

// ---------------- fused grouped 3x3 convs, 14-pixel tiles, f32x2 ----------
__global__ __launch_bounds__(96) void k_conv_fused(const float* __restrict__ xcl,
                                                   float* __restrict__ out3,
                                                   float* __restrict__ out2) {
    __shared__ float2 xsp[3][16][32];   // [dy][col][ic]: (x[ic], x[ic+32])
    int bid = blockIdx.x;
    int xt = bid & 3;
    int y  = (bid >> 2) % HH;
    int b  = bid / (4*HH);
    int x0 = xt * 14;
    int tid = threadIdx.x;

#pragma unroll
    for (int it = 0; it < 16; it++) {
        int i = tid + it*96;
        int ic  = i & 31;
        int col = (i >> 5) & 15;
        int dy  = i >> 9;
        int yy = y + dy - 1;
        int xx = x0 + col - 1;
        float v0 = 0.f, v1 = 0.f;
        if (yy >= 0 && yy < HH && xx >= 0 && xx < WW) {
            size_t base = ((size_t)((b*HH + yy)*WW + xx))*CC;
            v0 = xcl[base + ic];
            v1 = xcl[base + 32 + ic];
        }
        xsp[dy][col][ic] = make_float2(v0, v1);
    }
    __syncthreads();

    int t = tid;
    if (t < 74) {
        bool is3 = (t < 49);
        int o = is3 ? t : t - 49;
        int stride = is3 ? 49 : 25;
        const unsigned long long* wrow = is3 ? ((const unsigned long long*)g_wp3) + o
                                             : ((const unsigned long long*)g_wp2) + o;
        float2 bp = is3 ? g_bp3[o] : g_bp2[o];
        unsigned long long bdup;
        asm("mov.b64 %0, {%1, %2};" : "=l"(bdup) : "f"(bp.x), "f"(bp.y));

        unsigned long long acc[14];
#pragma unroll
        for (int p = 0; p < 14; p++) acc[p] = bdup;

#pragma unroll 2
        for (int ic = 0; ic < 32; ic++) {
            unsigned long long w2[9];
#pragma unroll
            for (int j = 0; j < 9; j++)
                w2[j] = wrow[(ic*9 + j)*stride];
#pragma unroll
            for (int dy = 0; dy < 3; dy++) {
                unsigned long long xm[16];
#pragma unroll
                for (int col = 0; col < 16; col++)
                    xm[col] = *(const unsigned long long*)&xsp[dy][col][ic];
#pragma unroll
                for (int dx = 0; dx < 3; dx++) {
                    unsigned long long wv = w2[dy*3 + dx];
#pragma unroll
                    for (int p = 0; p < 14; p++)
                        acc[p] = fma2(wv, xm[p+dx], acc[p]);
                }
            }
        }

        size_t pix = (size_t)(b*HH + y)*WW + x0;
        union { unsigned long long u; float f[2]; } cv;
        if (is3) {
#pragma unroll
            for (int p = 0; p < 14; p++) {
                cv.u = acc[p];
                out3[(pix + p)*98 + o]      = cv.f[0];
                out3[(pix + p)*98 + o + 49] = cv.f[1];
            }
        } else {
#pragma unroll
            for (int p = 0; p < 14; p++) {
                cv.u = acc[p];
                out2[(pix + p)*50 + o]      = cv.f[0];
                out2[(pix + p)*50 + o + 25] = cv.f[1];
            }
        }
    }
}

// ---------------- deformable depthwise conv: 4 px/warp, 8 ch/lane ---------
// 256 threads = 8 warps = 32 pixels per block. Lane owns 8 fp16 channels of
// one pixel (uint4 corner loads). Each tap: 4 corner LDG.128 serve 4 pixels
// (4 independent chains per warp). fp16 bilinear, fp32 weight-accumulate.
template<int K, int PAD, int DIL, bool WRITE_H>
__global__ __launch_bounds__(256) void k_deform(
                         const __half* __restrict__ src,  // NHWC fp16
                         const float* __restrict__ off,   // [pix][2*K*K]
                         const float* __restrict__ wt,    // [K*K][C] fp32
                         const float* __restrict__ bias,
                         float* __restrict__ outf,        // NHWC fp32
                         __half* __restrict__ outh,       // NHWC fp16 (optional)
                         float* __restrict__ bsum) {      // [NDB][CC] partials
    constexpr int K2 = K*K;
    constexpr int OFFC = 2*K2;
    __shared__ uint2 scoef[32][K2];    // {(hx,lx) half2, (hy,ly) half2} masked
    __shared__ int4  saddr[32][K2];
    __shared__ float sred[8][32][8];

    // phase 1: per-pixel per-tap coefficient + address precompute (block-wide)
    for (int i = threadIdx.x; i < 32*K2; i += 256) {
        int px = i / K2;
        int k  = i - px*K2;
        int gp = blockIdx.x*32 + px;
        int b = gp / HWP;
        int p = gp - b*HWP;
        int y = p / WW;
        int x = p - y*WW;
        float2 o2 = *(const float2*)(off + (size_t)gp*OFFC + 2*k);
        int ky = k / K, kx = k - ky*K;
        float py = (float)(y - PAD + DIL*ky) + o2.x;
        float px_ = (float)(x - PAD + DIL*kx) + o2.y;
        float fy = floorf(py), fx = floorf(px_);
        float ly = py - fy,  lx = px_ - fx;
        float hy = 1.f - ly, hx = 1.f - lx;
        int iy0 = (int)fy, ix0 = (int)fx;
        int iy1 = iy0 + 1, ix1 = ix0 + 1;
        float hxm = ((unsigned)ix0 < WW) ? hx : 0.f;
        float lxm = ((unsigned)ix1 < WW) ? lx : 0.f;
        float hym = ((unsigned)iy0 < HH) ? hy : 0.f;
        float lym = ((unsigned)iy1 < HH) ? ly : 0.f;
        int jy0 = min(max(iy0,0), HH-1), jy1 = min(max(iy1,0), HH-1);
        int jx0 = min(max(ix0,0), WW-1), jx1 = min(max(ix1,0), WW-1);
        scoef[px][k] = make_uint2(h2u(__floats2half2_rn(hxm, lxm)),
                                  h2u(__floats2half2_rn(hym, lym)));
        saddr[px][k] = make_int4((jy0*WW + jx0)*CC, (jy0*WW + jx1)*CC,
                                 (jy1*WW + jx0)*CC, (jy1*WW + jx1)*CC);
    }
    __syncthreads();

    int wid  = threadIdx.x >> 5;
    int lane = threadIdx.x & 31;
    int px   = (wid << 2) + (lane >> 3);   // pixel within block
    int c8   = (lane & 7) * 8;             // channel octet
    int gp   = blockIdx.x*32 + px;
    int b    = gp / HWP;
    const __half* sb = src + (size_t)b*HWP*CC + c8;
    const float*  wp = wt + c8;

    ulonglong2 accA = *(const ulonglong2*)(bias + c8);      // ch 0-3 of octet
    ulonglong2 accB = *(const ulonglong2*)(bias + c8 + 4);  // ch 4-7

#pragma unroll K
    for (int k = 0; k < K2; k++) {
        int4 ad = saddr[px][k];
        uint4 q00 = *(const uint4*)(sb + ad.x);
        uint4 q01 = *(const uint4*)(sb + ad.y);
        uint4 q10 = *(const uint4*)(sb + ad.z);
        uint4 q11 = *(const uint4*)(sb + ad.w);
        ulonglong2 wA = *(const ulonglong2*)(wp + k*CC);
        ulonglong2 wB = *(const ulonglong2*)(wp + k*CC + 4);
        uint2 cf = scoef[px][k];
        __half2 cx = u2h(cf.x), cy = u2h(cf.y);
        __half2 HX = __half2half2(__low2half(cx));
        __half2 LX = __half2half2(__high2half(cx));
        __half2 HY = __half2half2(__low2half(cy));
        __half2 LY = __half2half2(__high2half(cy));
        {   // ch 0-1
            __half2 top = __hfma2(LX, u2h(q01.x), __hmul2(HX, u2h(q00.x)));
            __half2 bot = __hfma2(LX, u2h(q11.x), __hmul2(HX, u2h(q10.x)));
            __half2 val = __hfma2(LY, bot, __hmul2(HY, top));
            accA.x = fma2(wA.x, h2f2(val), accA.x);
        }
        {   // ch 2-3
            __half2 top = __hfma2(LX, u2h(q01.y), __hmul2(HX, u2h(q00.y)));
            __half2 bot = __hfma2(LX, u2h(q11.y), __hmul2(HX, u2h(q10.y)));
            __half2 val = __hfma2(LY, bot, __hmul2(HY, top));
            accA.y = fma2(wA.y, h2f2(val), accA.y);
        }
        {   // ch 4-5
            __half2 top = __hfma2(LX, u2h(q01.z), __hmul2(HX, u2h(q00.z)));
            __half2 bot = __hfma2(LX, u2h(q11.z), __hmul2(HX, u2h(q10.z)));
            __half2 val = __hfma2(LY, bot, __hmul2(HY, top));
            accB.x = fma2(wB.x, h2f2(val), accB.x);
        }
        {   // ch 6-7
            __half2 top = __hfma2(LX, u2h(q01.w), __hmul2(HX, u2h(q00.w)));
            __half2 bot = __hfma2(LX, u2h(q11.w), __hmul2(HX, u2h(q10.w)));
            __half2 val = __hfma2(LY, bot, __hmul2(HY, top));
            accB.y = fma2(wB.y, h2f2(val), accB.y);
        }
    }

    *(ulonglong2*)(outf + (size_t)gp*CC + c8)     = accA;
    *(ulonglong2*)(outf + (size_t)gp*CC + c8 + 4) = accB;

    union { unsigned long long u; float f[2]; } a0, a1, a2, a3;
    a0.u = accA.x; a1.u = accA.y; a2.u = accB.x; a3.u = accB.y;

    if (WRITE_H) {
        uint4 st;
        st.x = h2u(__floats2half2_rn(a0.f[0], a0.f[1]));
        st.y = h2u(__floats2half2_rn(a1.f[0], a1.f[1]));
        st.z = h2u(__floats2half2_rn(a2.f[0], a2.f[1]));
        st.w = h2u(__floats2half2_rn(a3.f[0], a3.f[1]));
        *(uint4*)(outh + (size_t)gp*CC + c8) = st;
    }

    // ---- fused GAP partial: sum over the block's 32 pixels per channel ----
    float* sr = sred[wid][lane];
    sr[0] = a0.f[0]; sr[1] = a0.f[1]; sr[2] = a1.f[0]; sr[3] = a1.f[1];
    sr[4] = a2.f[0]; sr[5] = a2.f[1]; sr[6] = a3.f[0]; sr[7] = a3.f[1];
    __syncthreads();
    if (threadIdx.x < 64) {
        int c = threadIdx.x;
        int g = c >> 3, e = c & 7;
        float s = 0.f;
#pragma unroll
        for (int w = 0; w < 8; w++)
#pragma unroll
            for (int p = 0; p < 4; p++)
                s += sred[w][(p << 3) | g][e];
        bsum[(size_t)blockIdx.x*CC + c] = s;
    }
}

// ---------------- GAP finalize + softmax attn (from block partials) -------
__global__ void k_gap_final() {
    // grid = BB, 256 threads: q = ch quad, s = block-stride slot
    int b = blockIdx.x;
    int q = threadIdx.x & 15;
    int s = threadIdx.x >> 4;
    float4 a1 = make_float4(0,0,0,0), a2 = make_float4(0,0,0,0);
    for (int j = s; j < 98; j += 16) {
        size_t idx = (size_t)(b*98 + j)*CC + q*4;
        float4 v1 = *(const float4*)(g_bs1 + idx);
        float4 v2 = *(const float4*)(g_bs2 + idx);
        a1.x += v1.x; a1.y += v1.y; a1.z += v1.z; a1.w += v1.w;
        a2.x += v2.x; a2.y += v2.y; a2.z += v2.z; a2.w += v2.w;
    }
    __shared__ float4 sh1[16][16], sh2[16][16];
    sh1[s][q] = a1; sh2[s][q] = a2;
    __syncthreads();
    if (s == 0) {
#pragma unroll
        for (int j = 1; j < 16; j++) {
            float4 v1 = sh1[j][q], v2 = sh2[j][q];
            a1.x += v1.x; a1.y += v1.y; a1.z += v1.z; a1.w += v1.w;
            a2.x += v2.x; a2.y += v2.y; a2.z += v2.z; a2.w += v2.w;
        }
        float s1[4] = {a1.x, a1.y, a1.z, a1.w};
        float s2[4] = {a2.x, a2.y, a2.z, a2.w};
#pragma unroll
        for (int i = 0; i < 4; i++) {
            float g1 = s1[i] * (1.f/3136.f), g2 = s2[i] * (1.f/3136.f);
            float m = fmaxf(g1, g2);
            float e1 = expf(g1 - m), e2 = expf(g2 - m);
            g_attn[b*CC + q*4 + i] = e1 / (e1 + e2);
        }
    }
}

// ---------------- combine + NHWC -> NCHW ----------------
__global__ void k_combine(float* __restrict__ out) {
    __shared__ float tile[CC][33];
    int b  = blockIdx.x / 98;
    int p0 = (blockIdx.x % 98) * 32;
    int tid = threadIdx.x;
    int c = tid & 63;
    float a = g_attn[b*CC + c];
#pragma unroll
    for (int it = 0; it < 8; it++) {
        int pp = (tid >> 6) + it*4;
        size_t idx = ((size_t)(b*HWP + p0 + pp))*CC + c;
        float v1 = g_out1[idx], v2 = g_out2[idx];
        tile[c][pp] = v1*a + v2*(1.f - a);
    }
    __syncthreads();
#pragma unroll
    for (int it = 0; it < 8; it++) {
        int idx = tid + it*256;
        int cc = idx >> 5, pp = idx & 31;
        out[((size_t)(b*CC + cc))*HWP + p0 + pp] = tile[cc][pp];
    }
}

// ---------------- launcher ----------------
extern "C" void kernel_launch(void* const* d_in, const int* in_sizes, int n_in,
                              void* d_out, int out_size) {
    const float* x      = (const float*)d_in[0];
    const float* w_off3 = (const float*)d_in[1];
    const float* b_off3 = (const float*)d_in[2];
    const float* w_off2 = (const float*)d_in[3];
    const float* b_off2 = (const float*)d_in[4];
    const float* w7     = (const float*)d_in[5];
    const float* b7     = (const float*)d_in[6];
    const float* w5     = (const float*)d_in[7];
    const float* b5     = (const float*)d_in[8];
    float* out = (float*)d_out;

    float *p_xcl, *p_off3, *p_off2, *p_out1, *p_out2, *p_w7t, *p_w5t, *p_bs1, *p_bs2;
    __half *p_xh, *p_o1h;
    cudaGetSymbolAddress((void**)&p_xcl,  g_xcl);
    cudaGetSymbolAddress((void**)&p_xh,   g_xh);
    cudaGetSymbolAddress((void**)&p_o1h,  g_o1h);
    cudaGetSymbolAddress((void**)&p_off3, g_off3);
    cudaGetSymbolAddress((void**)&p_off2, g_off2);
    cudaGetSymbolAddress((void**)&p_out1, g_out1);
    cudaGetSymbolAddress((void**)&p_out2, g_out2);
    cudaGetSymbolAddress((void**)&p_w7t,  g_w7t);
    cudaGetSymbolAddress((void**)&p_w5t,  g_w5t);
    cudaGetSymbolAddress((void**)&p_bs1,  g_bs1);
    cudaGetSymbolAddress((void**)&p_bs2,  g_bs2);

    k_wprep<<<64, 256>>>(w7, w5, w_off3, b_off3, w_off2, b_off2);
    k_nchw2cl<<<BB*98, 256>>>(x);

    k_conv_fused<<<BB*HH*4, 96>>>(p_xcl, p_off3, p_off2);

    k_deform<7,9,3,true ><<<NDB, 256>>>(p_xh,  p_off3, p_w7t, b7, p_out1, p_o1h,   p_bs1);
    k_deform<5,6,3,false><<<NDB, 256>>>(p_o1h, p_off2, p_w5t, b5, p_out2, nullptr, p_bs2);

    k_gap_final<<<BB, 256>>>();
    k_combine<<<BB*98, 256>>>(out);
}

// round 9
// speedup vs baseline: 1.4157x; 1.0442x over previous
#include <cuda_runtime.h>
#include <cuda_fp16.h>

#define HH 56
#define WW 56
#define CC 64
#define BB 4
#define HWP 3136           // 56*56
#define NPIX (BB*HWP)      // 12544
#define NDB  (NPIX/32)     // deform blocks = 392 (98 per batch, 8x4 px tiles)

// ---------------- packed f32x2 helpers ----------------
__device__ __forceinline__ unsigned long long fma2(unsigned long long a, unsigned long long b, unsigned long long c) {
    unsigned long long d;
    asm("fma.rn.f32x2 %0, %1, %2, %3;" : "=l"(d) : "l"(a), "l"(b), "l"(c));
    return d;
}
__device__ __forceinline__ __half2 u2h(unsigned int v) { return *reinterpret_cast<__half2*>(&v); }
__device__ __forceinline__ unsigned int h2u(__half2 h) { return *reinterpret_cast<unsigned int*>(&h); }
// half2 -> packed f32x2 in 64-bit reg
__device__ __forceinline__ unsigned long long h2f2(__half2 hh) {
    float2 f = __half22float2(hh);
    unsigned long long d;
    asm("mov.b64 %0, {%1, %2};" : "=l"(d) : "f"(f.x), "f"(f.y));
    return d;
}

// ---------------- scratch (device globals; no allocations) ----------------
__device__ __align__(16) float g_xcl [NPIX*CC];      // x in NHWC fp32 (conv source)
__device__ __align__(16) __half g_xh [NPIX*CC];      // x in NHWC fp16 (deform1 gather src)
__device__ __align__(16) __half g_o1h[NPIX*CC];      // out1 NHWC fp16 (deform2 gather src)
__device__ __align__(16) float g_off3[NPIX*98];      // offset3 [pix][98]
__device__ __align__(16) float g_off2[NPIX*50];      // offset2 [pix][50]
__device__ __align__(16) float g_out1[NPIX*CC];      // out1 NHWC fp32
__device__ __align__(16) float g_out2[NPIX*CC];      // out2 NHWC fp32
__device__ __align__(16) float g_w7t [49*CC];        // w7 transposed [k][c]
__device__ __align__(16) float g_w5t [25*CC];        // w5 transposed [k][c]
__device__ __align__(16) float2 g_wp3[288*49];       // conv3 weight pairs [(ic*9+j)][o]
__device__ __align__(16) float2 g_wp2[288*25];       // conv2 weight pairs
__device__ __align__(16) float2 g_bp3[49];
__device__ __align__(16) float2 g_bp2[25];
__device__ __align__(16) float g_bs1[NDB*CC];        // per-block GAP partials (out1)
__device__ __align__(16) float g_bs2[NDB*CC];        // per-block GAP partials (out2)
__device__ __align__(16) float g_attn [BB*CC];

// ---------------- weight prep (grid-parallel) ----------------
__global__ void k_wprep(const float* __restrict__ w7, const float* __restrict__ w5,
                        const float* __restrict__ w_off3, const float* __restrict__ b_off3,
                        const float* __restrict__ w_off2, const float* __restrict__ b_off2) {
    int tid = blockIdx.x * blockDim.x + threadIdx.x;
    int nthr = gridDim.x * blockDim.x;
    for (int i = tid; i < CC*49; i += nthr) {
        int c = i / 49, k = i - c*49;
        g_w7t[k*CC + c] = w7[i];
    }
    for (int i = tid; i < CC*25; i += nthr) {
        int c = i / 25, k = i - c*25;
        g_w5t[k*CC + c] = w5[i];
    }
    for (int i = tid; i < 288*49; i += nthr) {
        int r = i / 49, o = i - r*49;
        int ic = r / 9, j = r - ic*9;
        g_wp3[i] = make_float2(w_off3[(o*32 + ic)*9 + j], w_off3[((o+49)*32 + ic)*9 + j]);
    }
    for (int i = tid; i < 288*25; i += nthr) {
        int r = i / 25, o = i - r*25;
        int ic = r / 9, j = r - ic*9;
        g_wp2[i] = make_float2(w_off2[(o*32 + ic)*9 + j], w_off2[((o+25)*32 + ic)*9 + j]);
    }
    if (tid < 49) g_bp3[tid] = make_float2(b_off3[tid], b_off3[tid+49]);
    if (tid >= 64 && tid < 89) g_bp2[tid-64] = make_float2(b_off2[tid-64], b_off2[tid-64+25]);
}

// ---------------- NCHW -> NHWC transpose of x (fp32 + fp16 copies) --------
__global__ void k_nchw2cl(const float* __restrict__ x) {
    __shared__ float tile[CC][33];
    int b  = blockIdx.x / 98;
    int p0 = (blockIdx.x % 98) * 32;
    int tid = threadIdx.x;
#pragma unroll
    for (int it = 0; it < 8; it++) {
        int idx = tid + it*256;
        int c = idx >> 5, pp = idx & 31;
        tile[c][pp] = x[((size_t)(b*CC + c))*HWP + p0 + pp];
    }
    __syncthreads();
    int c2 = tid & 63;
#pragma unroll
    for (int it = 0; it < 8; it++) {
        int pp2 = (tid >> 6) + it*4;
        float v = tile[c2][pp2];
        size_t idx = ((size_t)(b*HWP + p0 + pp2))*CC + c2;
        g_xcl[idx] = v;
        g_xh[idx]  = __float2half(v);
    }
}

// ---------------- fused grouped 3x3 convs, 14-pixel tiles, f32x2 ----------
__global__ __launch_bounds__(96) void k_conv_fused(const float* __restrict__ xcl,
                                                   float* __restrict__ out3,
                                                   float* __restrict__ out2) {
    __shared__ float2 xsp[3][16][32];   // [dy][col][ic]: (x[ic], x[ic+32])
    int bid = blockIdx.x;
    int xt = bid & 3;
    int y  = (bid >> 2) % HH;
    int b  = bid / (4*HH);
    int x0 = xt * 14;
    int tid = threadIdx.x;

#pragma unroll
    for (int it = 0; it < 16; it++) {
        int i = tid + it*96;
        int ic  = i & 31;
        int col = (i >> 5) & 15;
        int dy  = i >> 9;
        int yy = y + dy - 1;
        int xx = x0 + col - 1;
        float v0 = 0.f, v1 = 0.f;
        if (yy >= 0 && yy < HH && xx >= 0 && xx < WW) {
            size_t base = ((size_t)((b*HH + yy)*WW + xx))*CC;
            v0 = xcl[base + ic];
            v1 = xcl[base + 32 + ic];
        }
        xsp[dy][col][ic] = make_float2(v0, v1);
    }
    __syncthreads();

    int t = tid;
    if (t < 74) {
        bool is3 = (t < 49);
        int o = is3 ? t : t - 49;
        int stride = is3 ? 49 : 25;
        const unsigned long long* wrow = is3 ? ((const unsigned long long*)g_wp3) + o
                                             : ((const unsigned long long*)g_wp2) + o;
        float2 bp = is3 ? g_bp3[o] : g_bp2[o];
        unsigned long long bdup;
        asm("mov.b64 %0, {%1, %2};" : "=l"(bdup) : "f"(bp.x), "f"(bp.y));

        unsigned long long acc[14];
#pragma unroll
        for (int p = 0; p < 14; p++) acc[p] = bdup;

#pragma unroll 2
        for (int ic = 0; ic < 32; ic++) {
            unsigned long long w2[9];
#pragma unroll
            for (int j = 0; j < 9; j++)
                w2[j] = wrow[(ic*9 + j)*stride];
#pragma unroll
            for (int dy = 0; dy < 3; dy++) {
                unsigned long long xm[16];
#pragma unroll
                for (int col = 0; col < 16; col++)
                    xm[col] = *(const unsigned long long*)&xsp[dy][col][ic];
#pragma unroll
                for (int dx = 0; dx < 3; dx++) {
                    unsigned long long wv = w2[dy*3 + dx];
#pragma unroll
                    for (int p = 0; p < 14; p++)
                        acc[p] = fma2(wv, xm[p+dx], acc[p]);
                }
            }
        }

        size_t pix = (size_t)(b*HH + y)*WW + x0;
        union { unsigned long long u; float f[2]; } cv;
        if (is3) {
#pragma unroll
            for (int p = 0; p < 14; p++) {
                cv.u = acc[p];
                out3[(pix + p)*98 + o]      = cv.f[0];
                out3[(pix + p)*98 + o + 49] = cv.f[1];
            }
        } else {
#pragma unroll
            for (int p = 0; p < 14; p++) {
                cv.u = acc[p];
                out2[(pix + p)*50 + o]      = cv.f[0];
                out2[(pix + p)*50 + o + 25] = cv.f[1];
            }
        }
    }
}

// ---------------- deformable depthwise conv: 8x4 px tile per block --------
// 512 threads = 16 warps; warp owns TWO pixels (half-warp each); lane owns
// 4 fp16 channels. Block = spatial 8x4 tile -> gather footprint ~73KB,
// ~2.65 blocks/SM -> L1-resident. Per-tap smem record = ONE uint4:
// {(hx,lx)half2, (hy,ly)half2, a00, (dy<<16)|dx}; corners at a00+{0,dx,dy,dy+dx}.
template<int K, int PAD, int DIL, bool WRITE_H>
__global__ __launch_bounds__(512) void k_deform(
                         const __half* __restrict__ src,  // NHWC fp16
                         const float* __restrict__ off,   // [pix][2*K*K]
                         const float* __restrict__ wt,    // [K*K][C] fp32
                         const float* __restrict__ bias,
                         float* __restrict__ outf,        // NHWC fp32
                         __half* __restrict__ outh,       // NHWC fp16 (optional)
                         float* __restrict__ bsum) {      // [NDB][CC] partials
    constexpr int K2 = K*K;
    constexpr int OFFC = 2*K2;
    __shared__ uint4  stap[32][K2];
    __shared__ float4 sred[16][16];

    int tile = blockIdx.x;
    int b  = tile / 98;
    int tt = tile - b*98;
    int ty = tt / 7, tx = tt - ty*7;
    int y0 = ty*4, x0 = tx*8;

    // phase 1: per-pixel per-tap coefficient + address precompute
    for (int i = threadIdx.x; i < 32*K2; i += 512) {
        int px = i / K2;
        int k  = i - px*K2;
        int y = y0 + (px >> 3);
        int x = x0 + (px & 7);
        int gp = (b*HH + y)*WW + x;
        float2 o2 = *(const float2*)(off + (size_t)gp*OFFC + 2*k);
        int ky = k / K, kx = k - ky*K;
        float py = (float)(y - PAD + DIL*ky) + o2.x;
        float px_ = (float)(x - PAD + DIL*kx) + o2.y;
        float fy = floorf(py), fx = floorf(px_);
        float ly = py - fy,  lx = px_ - fx;
        float hy = 1.f - ly, hx = 1.f - lx;
        int iy0 = (int)fy, ix0 = (int)fx;
        int iy1 = iy0 + 1, ix1 = ix0 + 1;
        float hxm = ((unsigned)ix0 < WW) ? hx : 0.f;
        float lxm = ((unsigned)ix1 < WW) ? lx : 0.f;
        float hym = ((unsigned)iy0 < HH) ? hy : 0.f;
        float lym = ((unsigned)iy1 < HH) ? ly : 0.f;
        int jy0 = min(max(iy0,0), HH-1), jy1 = min(max(iy1,0), HH-1);
        int jx0 = min(max(ix0,0), WW-1), jx1 = min(max(ix1,0), WW-1);
        int a00 = (jy0*WW + jx0)*CC;
        int dxo = (jx1 - jx0)*CC;            // 0 or 64
        int dyo = (jy1 - jy0)*WW*CC;         // 0 or 3584 (fits 16 bits)
        stap[px][k] = make_uint4(h2u(__floats2half2_rn(hxm, lxm)),
                                 h2u(__floats2half2_rn(hym, lym)),
                                 (unsigned)a00,
                                 ((unsigned)dyo << 16) | (unsigned)dxo);
    }
    __syncthreads();

    int wid  = threadIdx.x >> 5;
    int lane = threadIdx.x & 31;
    int half_ = lane >> 4;
    int q = lane & 15;
    int p2 = (wid << 1) + half_;           // pixel within tile
    int y = y0 + (p2 >> 3);
    int x = x0 + (p2 & 7);
    int gp = (b*HH + y)*WW + x;
    int c4 = q*4;
    const __half* sb = src + (size_t)b*HWP*CC + c4;
    const float*  wp = wt + c4;

    ulonglong2 acc = *(const ulonglong2*)(bias + c4);

#pragma unroll
    for (int k = 0; k < K2; k++) {
        uint4 tp = *((const uint4*)&stap[p2][k]);   // one LDS.128
        int a00 = (int)tp.z;
        int dxo = (int)(tp.w & 0xffffu);
        int dyo = (int)(tp.w >> 16);
        const __half* r0 = sb + a00;
        uint2 q00 = *(const uint2*)(r0);
        uint2 q01 = *(const uint2*)(r0 + dxo);
        uint2 q10 = *(const uint2*)(r0 + dyo);
        uint2 q11 = *(const uint2*)(r0 + dyo + dxo);
        ulonglong2 wv = *(const ulonglong2*)(wp + k*CC);
        __half2 cx = u2h(tp.x), cy = u2h(tp.y);
        __half2 HX = __half2half2(__low2half(cx));
        __half2 LX = __half2half2(__high2half(cx));
        __half2 HY = __half2half2(__low2half(cy));
        __half2 LY = __half2half2(__high2half(cy));
        {   // ch 0-1
            __half2 top = __hfma2(LX, u2h(q01.x), __hmul2(HX, u2h(q00.x)));
            __half2 bot = __hfma2(LX, u2h(q11.x), __hmul2(HX, u2h(q10.x)));
            __half2 val = __hfma2(LY, bot, __hmul2(HY, top));
            acc.x = fma2(wv.x, h2f2(val), acc.x);
        }
        {   // ch 2-3
            __half2 top = __hfma2(LX, u2h(q01.y), __hmul2(HX, u2h(q00.y)));
            __half2 bot = __hfma2(LX, u2h(q11.y), __hmul2(HX, u2h(q10.y)));
            __half2 val = __hfma2(LY, bot, __hmul2(HY, top));
            acc.y = fma2(wv.y, h2f2(val), acc.y);
        }
    }
    *(ulonglong2*)(outf + (size_t)gp*CC + c4) = acc;

    union { unsigned long long u; float f[2]; } a0, a1;
    a0.u = acc.x; a1.u = acc.y;
    if (WRITE_H) {
        uint2 st;
        st.x = h2u(__floats2half2_rn(a0.f[0], a0.f[1]));
        st.y = h2u(__floats2half2_rn(a1.f[0], a1.f[1]));
        *(uint2*)(outh + (size_t)gp*CC + c4) = st;
    }

    // ---- fused GAP partial: per-block channel sums over 32 pixels ----
    float4 v = make_float4(a0.f[0], a0.f[1], a1.f[0], a1.f[1]);
    v.x += __shfl_xor_sync(0xffffffffu, v.x, 16);
    v.y += __shfl_xor_sync(0xffffffffu, v.y, 16);
    v.z += __shfl_xor_sync(0xffffffffu, v.z, 16);
    v.w += __shfl_xor_sync(0xffffffffu, v.w, 16);
    if (half_ == 0) sred[wid][q] = v;
    __syncthreads();
    if (threadIdx.x < 64) {
        int c = threadIdx.x;
        int qq = c >> 2, e = c & 3;
        float s = 0.f;
#pragma unroll
        for (int w = 0; w < 16; w++) {
            const float* f4 = (const float*)&sred[w][qq];
            s += f4[e];
        }
        bsum[(size_t)blockIdx.x*CC + c] = s;
    }
}

// ---------------- GAP finalize + softmax attn (from block partials) -------
__global__ void k_gap_final() {
    // grid = BB, 256 threads: q = ch quad, s = block-stride slot
    int b = blockIdx.x;
    int q = threadIdx.x & 15;
    int s = threadIdx.x >> 4;
    float4 a1 = make_float4(0,0,0,0), a2 = make_float4(0,0,0,0);
    for (int j = s; j < 98; j += 16) {
        size_t idx = (size_t)(b*98 + j)*CC + q*4;
        float4 v1 = *(const float4*)(g_bs1 + idx);
        float4 v2 = *(const float4*)(g_bs2 + idx);
        a1.x += v1.x; a1.y += v1.y; a1.z += v1.z; a1.w += v1.w;
        a2.x += v2.x; a2.y += v2.y; a2.z += v2.z; a2.w += v2.w;
    }
    __shared__ float4 sh1[16][16], sh2[16][16];
    sh1[s][q] = a1; sh2[s][q] = a2;
    __syncthreads();
    if (s == 0) {
#pragma unroll
        for (int j = 1; j < 16; j++) {
            float4 v1 = sh1[j][q], v2 = sh2[j][q];
            a1.x += v1.x; a1.y += v1.y; a1.z += v1.z; a1.w += v1.w;
            a2.x += v2.x; a2.y += v2.y; a2.z += v2.z; a2.w += v2.w;
        }
        float s1[4] = {a1.x, a1.y, a1.z, a1.w};
        float s2[4] = {a2.x, a2.y, a2.z, a2.w};
#pragma unroll
        for (int i = 0; i < 4; i++) {
            float g1 = s1[i] * (1.f/3136.f), g2 = s2[i] * (1.f/3136.f);
            float m = fmaxf(g1, g2);
            float e1 = expf(g1 - m), e2 = expf(g2 - m);
            g_attn[b*CC + q*4 + i] = e1 / (e1 + e2);
        }
    }
}

// ---------------- combine + NHWC -> NCHW ----------------
__global__ void k_combine(float* __restrict__ out) {
    __shared__ float tile[CC][33];
    int b  = blockIdx.x / 98;
    int p0 = (blockIdx.x % 98) * 32;
    int tid = threadIdx.x;
    int c = tid & 63;
    float a = g_attn[b*CC + c];
#pragma unroll
    for (int it = 0; it < 8; it++) {
        int pp = (tid >> 6) + it*4;
        size_t idx = ((size_t)(b*HWP + p0 + pp))*CC + c;
        float v1 = g_out1[idx], v2 = g_out2[idx];
        tile[c][pp] = v1*a + v2*(1.f - a);
    }
    __syncthreads();
#pragma unroll
    for (int it = 0; it < 8; it++) {
        int idx = tid + it*256;
        int cc = idx >> 5, pp = idx & 31;
        out[((size_t)(b*CC + cc))*HWP + p0 + pp] = tile[cc][pp];
    }
}

// ---------------- launcher ----------------
extern "C" void kernel_launch(void* const* d_in, const int* in_sizes, int n_in,
                              void* d_out, int out_size) {
    const float* x      = (const float*)d_in[0];
    const float* w_off3 = (const float*)d_in[1];
    const float* b_off3 = (const float*)d_in[2];
    const float* w_off2 = (const float*)d_in[3];
    const float* b_off2 = (const float*)d_in[4];
    const float* w7     = (const float*)d_in[5];
    const float* b7     = (const float*)d_in[6];
    const float* w5     = (const float*)d_in[7];
    const float* b5     = (const float*)d_in[8];
    float* out = (float*)d_out;

    float *p_xcl, *p_off3, *p_off2, *p_out1, *p_out2, *p_w7t, *p_w5t, *p_bs1, *p_bs2;
    __half *p_xh, *p_o1h;
    cudaGetSymbolAddress((void**)&p_xcl,  g_xcl);
    cudaGetSymbolAddress((void**)&p_xh,   g_xh);
    cudaGetSymbolAddress((void**)&p_o1h,  g_o1h);
    cudaGetSymbolAddress((void**)&p_off3, g_off3);
    cudaGetSymbolAddress((void**)&p_off2, g_off2);
    cudaGetSymbolAddress((void**)&p_out1, g_out1);
    cudaGetSymbolAddress((void**)&p_out2, g_out2);
    cudaGetSymbolAddress((void**)&p_w7t,  g_w7t);
    cudaGetSymbolAddress((void**)&p_w5t,  g_w5t);
    cudaGetSymbolAddress((void**)&p_bs1,  g_bs1);
    cudaGetSymbolAddress((void**)&p_bs2,  g_bs2);

    k_wprep<<<64, 256>>>(w7, w5, w_off3, b_off3, w_off2, b_off2);
    k_nchw2cl<<<BB*98, 256>>>(x);

    k_conv_fused<<<BB*HH*4, 96>>>(p_xcl, p_off3, p_off2);

    k_deform<7,9,3,true ><<<NDB, 512>>>(p_xh,  p_off3, p_w7t, b7, p_out1, p_o1h,   p_bs1);
    k_deform<5,6,3,false><<<NDB, 512>>>(p_o1h, p_off2, p_w5t, b5, p_out2, nullptr, p_bs2);

    k_gap_final<<<BB, 256>>>();
    k_combine<<<BB*98, 256>>>(out);
}